// round 8
// baseline (speedup 1.0000x reference)
#include <cuda_runtime.h>

typedef unsigned long long ull;

#define CDIM 512
#define MDIM 320
#define LCLS 10
#define SHRINK_L 0.0025f
#define EPS_F 1e-12f

#define BM 64
#define THREADS 256

// shared memory layout (float offsets)
#define OFF_ATT 0            // 64*320  = 20480 floats
#define OFF_SEM 20480        // 10*512  = 5120
#define OFF_WS  25600        // 32*322  = 10304 (also reused as 32*260)
#define OFF_XS  35904        // 64*36   = 2304
#define SMEM_FLOATS 38208
#define WS_STRIDE  322
#define WS2_STRIDE 260
#define XS_STRIDE  36

__device__ float g_sem[LCLS * CDIM];

__device__ __forceinline__ float sigmoidf_(float x) { return 1.0f / (1.0f + __expf(-x)); }

__device__ __forceinline__ ull pack2(float lo, float hi) {
    ull r; asm("mov.b64 %0, {%1, %2};" : "=l"(r) : "f"(lo), "f"(hi)); return r;
}
__device__ __forceinline__ void unpack2(ull v, float& lo, float& hi) {
    asm("mov.b64 {%0, %1}, %2;" : "=f"(lo), "=f"(hi) : "l"(v));
}
__device__ __forceinline__ void ffma2(ull& d, ull a, ull b) {
    asm("fma.rn.f32x2 %0, %1, %2, %0;" : "+l"(d) : "l"(a), "l"(b));
}

__device__ __forceinline__ float wr_max(float v) {
    #pragma unroll
    for (int o = 16; o; o >>= 1) v = fmaxf(v, __shfl_xor_sync(0xffffffffu, v, o));
    return v;
}
__device__ __forceinline__ float wr_sum(float v) {
    #pragma unroll
    for (int o = 16; o; o >>= 1) v += __shfl_xor_sync(0xffffffffu, v, o);
    return v;
}

// ---------------------------------------------------------------------------
// Kernel A: build sem_att [10, 512] from W, wp, bp, wi, bi. One block, 512 thr.
// rp[n,p,c] = W_flat[n*2048 + c*4 + p]
// part[n,c] = mean_q sigmoid(sum_p wp[q,p]*rp[n,p,c] + bp[q]) * rp[n,q,c]
// sem[l,c]  = mean_q sigmoid(sum_t wi[q,t]*part[l*8+t,c] + bi[q]) * part[l*8+q,c]
// ---------------------------------------------------------------------------
__global__ void sem_build_kernel(const float* __restrict__ W,
                                 const float* __restrict__ wp,
                                 const float* __restrict__ bp,
                                 const float* __restrict__ wi,
                                 const float* __restrict__ bi,
                                 float* __restrict__ out_semmat) {
    int c = threadIdx.x;
    if (c >= CDIM) return;

    float wpl[16], bpl[4], wil[64], bil[8];
    #pragma unroll
    for (int i = 0; i < 16; ++i) wpl[i] = wp[i];
    #pragma unroll
    for (int i = 0; i < 4; ++i) bpl[i] = bp[i];
    #pragma unroll
    for (int i = 0; i < 64; ++i) wil[i] = wi[i];
    #pragma unroll
    for (int i = 0; i < 8; ++i) bil[i] = bi[i];

    for (int l = 0; l < LCLS; ++l) {
        float pt[8];
        #pragma unroll
        for (int t = 0; t < 8; ++t) {
            int n = l * 8 + t;
            float4 r4 = *(const float4*)(W + n * 2048 + c * 4);
            float rp[4] = {r4.x, r4.y, r4.z, r4.w};
            float acc = 0.0f;
            #pragma unroll
            for (int q = 0; q < 4; ++q) {
                float s = bpl[q];
                #pragma unroll
                for (int p = 0; p < 4; ++p) s += wpl[q * 4 + p] * rp[p];
                acc += sigmoidf_(s) * rp[q];
            }
            pt[t] = acc * 0.25f;
        }
        float acc2 = 0.0f;
        #pragma unroll
        for (int q = 0; q < 8; ++q) {
            float s = bil[q];
            #pragma unroll
            for (int t = 0; t < 8; ++t) s += wil[q * 8 + t] * pt[t];
            acc2 += sigmoidf_(s) * pt[q];
        }
        float v = acc2 * 0.125f;
        g_sem[l * CDIM + c] = v;
        out_semmat[l * CDIM + c] = v;
    }
}

// ---------------------------------------------------------------------------
// Kernel B: per 64-row tile — stage-3 attend (sem), then fused
// softmax(X@Wt) -> shrink -> L1 -> @W   (part-level attend)
// ---------------------------------------------------------------------------
__global__ __launch_bounds__(THREADS, 1)
void fused_attend_kernel(const float* __restrict__ X,
                         const float* __restrict__ W,
                         float* __restrict__ out_sem,
                         float* __restrict__ out_att,
                         float* __restrict__ out_part) {
    extern __shared__ float sm[];
    float* ATTs = sm + OFF_ATT;
    float* SEMs = sm + OFF_SEM;
    float* WSs  = sm + OFF_WS;
    float* XSs  = sm + OFF_XS;

    const int tid = threadIdx.x;
    const int tc = tid & 31;
    const int tr = tid >> 5;
    const int rowbase = blockIdx.x * BM;

    // load sem_att into smem
    for (int t = tid; t < LCLS * CDIM / 4; t += THREADS)
        *(float4*)&SEMs[t * 4] = *(const float4*)&g_sem[t * 4];
    __syncthreads();

    // ------------------- stage 3: attend over sem (L=10) -------------------
    #pragma unroll
    for (int i2 = 0; i2 < 2; ++i2) {
        float s3[4][10];
        #pragma unroll
        for (int k = 0; k < 4; ++k)
            #pragma unroll
            for (int l = 0; l < 10; ++l) s3[k][l] = 0.0f;

        #pragma unroll 4
        for (int u = 0; u < 16; ++u) {
            int cc = u * 32 + tc;
            float xv[4];
            #pragma unroll
            for (int k = 0; k < 4; ++k)
                xv[k] = X[(rowbase + tr * 8 + i2 * 4 + k) * CDIM + cc];
            #pragma unroll
            for (int l = 0; l < 10; ++l) {
                float sv = SEMs[l * CDIM + cc];
                #pragma unroll
                for (int k = 0; k < 4; ++k) s3[k][l] += xv[k] * sv;
            }
        }
        #pragma unroll
        for (int k = 0; k < 4; ++k) {
            #pragma unroll
            for (int l = 0; l < 10; ++l) s3[k][l] = wr_sum(s3[k][l]);
            float mx = s3[k][0];
            #pragma unroll
            for (int l = 1; l < 10; ++l) mx = fmaxf(mx, s3[k][l]);
            float se = 0.0f;
            #pragma unroll
            for (int l = 0; l < 10; ++l) { s3[k][l] = __expf(s3[k][l] - mx); se += s3[k][l]; }
            float inv = 1.0f / se;
            float l1 = 0.0f;
            #pragma unroll
            for (int l = 0; l < 10; ++l) {
                float a = s3[k][l] * inv;
                float t = a - SHRINK_L;
                float v = fmaxf(t, 0.0f) * a / (fabsf(t) + EPS_F);
                s3[k][l] = v; l1 += v;
            }
            float sc = 1.0f / fmaxf(l1, EPS_F);
            #pragma unroll
            for (int l = 0; l < 10; ++l) s3[k][l] *= sc;
            int rg = rowbase + tr * 8 + i2 * 4 + k;
            if (tc == 0) {
                #pragma unroll
                for (int l = 0; l < 10; ++l) out_att[rg * 10 + l] = s3[k][l];
            }
        }
        // readout with sem
        #pragma unroll 4
        for (int u = 0; u < 16; ++u) {
            int cc = u * 32 + tc;
            float acc[4] = {0.0f, 0.0f, 0.0f, 0.0f};
            #pragma unroll
            for (int l = 0; l < 10; ++l) {
                float sv = SEMs[l * CDIM + cc];
                #pragma unroll
                for (int k = 0; k < 4; ++k) acc[k] += s3[k][l] * sv;
            }
            #pragma unroll
            for (int k = 0; k < 4; ++k)
                out_sem[(rowbase + tr * 8 + i2 * 4 + k) * CDIM + cc] = acc[k];
        }
    }

    // ------------------- GEMM1: S[64,320] = X_tile @ W^T -------------------
    ull acc[8][5];
    #pragma unroll
    for (int i = 0; i < 8; ++i)
        #pragma unroll
        for (int j = 0; j < 5; ++j) acc[i][j] = 0ULL;

    for (int k0 = 0; k0 < CDIM; k0 += 32) {
        __syncthreads();
        // W tile, k-major in smem: WSs[kk][m], stride 322
        #pragma unroll
        for (int it = 0; it < 10; ++it) {
            int q = tid + it * THREADS;       // q < 2560
            int m = q >> 3, kq = q & 7;
            float4 w4 = *(const float4*)&W[m * CDIM + k0 + kq * 4];
            float* d = &WSs[(kq * 4) * WS_STRIDE + m];
            d[0] = w4.x; d[WS_STRIDE] = w4.y; d[2 * WS_STRIDE] = w4.z; d[3 * WS_STRIDE] = w4.w;
        }
        // X tile: XSs[r][kk], stride 36
        #pragma unroll
        for (int it = 0; it < 2; ++it) {
            int q = tid + it * THREADS;       // q < 512
            int r = q >> 3, kq = q & 7;
            float4 x4 = *(const float4*)&X[(rowbase + r) * CDIM + k0 + kq * 4];
            *(float4*)&XSs[r * XS_STRIDE + kq * 4] = x4;
        }
        __syncthreads();

        #pragma unroll 4
        for (int kk = 0; kk < 32; ++kk) {
            ull ap[8];
            #pragma unroll
            for (int i = 0; i < 8; ++i) {
                float a = XSs[(tr * 8 + i) * XS_STRIDE + kk];
                ap[i] = pack2(a, a);
            }
            #pragma unroll
            for (int j = 0; j < 5; ++j) {
                ull b = *(const ull*)&WSs[kk * WS_STRIDE + j * 64 + tc * 2];
                #pragma unroll
                for (int i = 0; i < 8; ++i) ffma2(acc[i][j], ap[i], b);
            }
        }
    }

    // --------- epilogue: softmax over 320, shrink, L1, to ATTs smem ---------
    #pragma unroll
    for (int i = 0; i < 8; ++i) {
        float sv[10];
        #pragma unroll
        for (int j = 0; j < 5; ++j) unpack2(acc[i][j], sv[2 * j], sv[2 * j + 1]);
        float mx = sv[0];
        #pragma unroll
        for (int x = 1; x < 10; ++x) mx = fmaxf(mx, sv[x]);
        mx = wr_max(mx);
        float se = 0.0f;
        #pragma unroll
        for (int x = 0; x < 10; ++x) { sv[x] = __expf(sv[x] - mx); se += sv[x]; }
        se = wr_sum(se);
        float inv = 1.0f / se;
        float l1 = 0.0f;
        #pragma unroll
        for (int x = 0; x < 10; ++x) {
            float a = sv[x] * inv;
            float t = a - SHRINK_L;
            float v = fmaxf(t, 0.0f) * a / (fabsf(t) + EPS_F);
            sv[x] = v; l1 += v;
        }
        l1 = wr_sum(l1);
        float sc = 1.0f / fmaxf(l1, EPS_F);
        #pragma unroll
        for (int j = 0; j < 5; ++j) {
            float2 p; p.x = sv[2 * j] * sc; p.y = sv[2 * j + 1] * sc;
            *(float2*)&ATTs[(tr * 8 + i) * MDIM + j * 64 + tc * 2] = p;
        }
    }

    // ------------- readout GEMM: O[64,512] = ATTs[64,320] @ W --------------
    #pragma unroll
    for (int ct = 0; ct < 2; ++ct) {
        ull acc2[8][4];
        #pragma unroll
        for (int i = 0; i < 8; ++i)
            #pragma unroll
            for (int j = 0; j < 4; ++j) acc2[i][j] = 0ULL;

        for (int k0 = 0; k0 < MDIM; k0 += 32) {
            __syncthreads();
            // W rows k0..k0+31, col half ct: WSs[kk][cc], stride 260
            #pragma unroll
            for (int it = 0; it < 8; ++it) {
                int q = tid + it * THREADS;   // q < 2048
                int kk = q >> 6, cc = (q & 63) << 2;
                *(float4*)&WSs[kk * WS2_STRIDE + cc] =
                    *(const float4*)&W[(k0 + kk) * CDIM + ct * 256 + cc];
            }
            __syncthreads();

            #pragma unroll 4
            for (int kk = 0; kk < 32; ++kk) {
                ull ap[8];
                #pragma unroll
                for (int i = 0; i < 8; ++i) {
                    float a = ATTs[(tr * 8 + i) * MDIM + k0 + kk];
                    ap[i] = pack2(a, a);
                }
                #pragma unroll
                for (int j = 0; j < 4; ++j) {
                    ull b = *(const ull*)&WSs[kk * WS2_STRIDE + j * 64 + tc * 2];
                    #pragma unroll
                    for (int i = 0; i < 8; ++i) ffma2(acc2[i][j], ap[i], b);
                }
            }
        }
        #pragma unroll
        for (int i = 0; i < 8; ++i) {
            int rg = rowbase + tr * 8 + i;
            #pragma unroll
            for (int j = 0; j < 4; ++j) {
                float lo, hi; unpack2(acc2[i][j], lo, hi);
                float2 p; p.x = lo; p.y = hi;
                *(float2*)&out_part[rg * CDIM + ct * 256 + j * 64 + tc * 2] = p;
            }
        }
    }
}

extern "C" void kernel_launch(void* const* d_in, const int* in_sizes, int n_in,
                              void* d_out, int out_size) {
    const float* X  = (const float*)d_in[0];
    const float* W  = (const float*)d_in[1];
    const float* wp = (const float*)d_in[2];
    const float* bp = (const float*)d_in[3];
    const float* wi = (const float*)d_in[4];
    const float* bi = (const float*)d_in[5];

    int N = in_sizes[0] / CDIM;   // 131072

    float* out       = (float*)d_out;
    float* out_sem   = out;                                   // [N, 512]
    float* out_att   = out + (size_t)N * CDIM;                // [N, 10]
    float* out_semm  = out_att + (size_t)N * LCLS;            // [10, 512]
    float* out_part  = out_semm + (size_t)LCLS * CDIM;        // [N, 512]

    sem_build_kernel<<<1, 512>>>(W, wp, bp, wi, bi, out_semm);

    int smem_bytes = SMEM_FLOATS * 4;
    cudaFuncSetAttribute(fused_attend_kernel,
                         cudaFuncAttributeMaxDynamicSharedMemorySize, smem_bytes);
    fused_attend_kernel<<<N / BM, THREADS, smem_bytes>>>(X, W, out_sem, out_att, out_part);
}

// round 10
// speedup vs baseline: 1.6109x; 1.6109x over previous
#include <cuda_runtime.h>

typedef unsigned long long ull;

#define CDIM 512
#define MDIM 320
#define LCLS 10
#define SHRINK_L 0.0025f
#define EPS_F 1e-12f

#define BM 64
#define THREADS 256

// shared memory layout (float offsets)
#define OFF_ATT 0            // 64*320  = 20480 floats
#define OFF_SEM 20480        // 10*512  = 5120
#define OFF_WS  25600        // 32*322  = 10304 (also reused as 32*260)
#define OFF_XS  35904        // 64*36   = 2304
#define SMEM_FLOATS 38208
#define WS_STRIDE  322
#define WS2_STRIDE 260
#define XS_STRIDE  36

__device__ float g_sem[LCLS * CDIM];

__device__ __forceinline__ float sigmoidf_(float x) { return 1.0f / (1.0f + __expf(-x)); }

__device__ __forceinline__ ull pack2(float lo, float hi) {
    ull r; asm("mov.b64 %0, {%1, %2};" : "=l"(r) : "f"(lo), "f"(hi)); return r;
}
__device__ __forceinline__ void unpack2(ull v, float& lo, float& hi) {
    asm("mov.b64 {%0, %1}, %2;" : "=f"(lo), "=f"(hi) : "l"(v));
}
__device__ __forceinline__ void ffma2(ull& d, ull a, ull b) {
    asm("fma.rn.f32x2 %0, %1, %2, %0;" : "+l"(d) : "l"(a), "l"(b));
}

__device__ __forceinline__ float wr_max(float v) {
    #pragma unroll
    for (int o = 16; o; o >>= 1) v = fmaxf(v, __shfl_xor_sync(0xffffffffu, v, o));
    return v;
}
__device__ __forceinline__ float wr_sum(float v) {
    #pragma unroll
    for (int o = 16; o; o >>= 1) v += __shfl_xor_sync(0xffffffffu, v, o);
    return v;
}

// ---------------------------------------------------------------------------
// Kernel A: build sem_att [10, 512] from W, wp, bp, wi, bi. One block, 512 thr.
// rp[n,p,c] = W_flat[n*2048 + c*4 + p]
// part[n,c] = mean_q sigmoid(sum_p wp[q,p]*rp[n,p,c] + bp[q]) * rp[n,q,c]
// sem[l,c]  = mean_q sigmoid(sum_t wi[q,t]*part[l*8+t,c] + bi[q]) * part[l*8+q,c]
// ---------------------------------------------------------------------------
__global__ void sem_build_kernel(const float* __restrict__ W,
                                 const float* __restrict__ wp,
                                 const float* __restrict__ bp,
                                 const float* __restrict__ wi,
                                 const float* __restrict__ bi,
                                 float* __restrict__ out_semmat) {
    int c = threadIdx.x;
    if (c >= CDIM) return;

    float wpl[16], bpl[4], wil[64], bil[8];
    #pragma unroll
    for (int i = 0; i < 16; ++i) wpl[i] = wp[i];
    #pragma unroll
    for (int i = 0; i < 4; ++i) bpl[i] = bp[i];
    #pragma unroll
    for (int i = 0; i < 64; ++i) wil[i] = wi[i];
    #pragma unroll
    for (int i = 0; i < 8; ++i) bil[i] = bi[i];

    for (int l = 0; l < LCLS; ++l) {
        float pt[8];
        #pragma unroll
        for (int t = 0; t < 8; ++t) {
            int n = l * 8 + t;
            float4 r4 = *(const float4*)(W + n * 2048 + c * 4);
            float rp[4] = {r4.x, r4.y, r4.z, r4.w};
            float acc = 0.0f;
            #pragma unroll
            for (int q = 0; q < 4; ++q) {
                float s = bpl[q];
                #pragma unroll
                for (int p = 0; p < 4; ++p) s += wpl[q * 4 + p] * rp[p];
                acc += sigmoidf_(s) * rp[q];
            }
            pt[t] = acc * 0.25f;
        }
        float acc2 = 0.0f;
        #pragma unroll
        for (int q = 0; q < 8; ++q) {
            float s = bil[q];
            #pragma unroll
            for (int t = 0; t < 8; ++t) s += wil[q * 8 + t] * pt[t];
            acc2 += sigmoidf_(s) * pt[q];
        }
        float v = acc2 * 0.125f;
        g_sem[l * CDIM + c] = v;
        out_semmat[l * CDIM + c] = v;
    }
}

// ---------------------------------------------------------------------------
// Kernel B: per 64-row tile — stage-3 attend (sem), then fused
// softmax(X@Wt) -> shrink -> L1 -> @W   (part-level attend)
// ---------------------------------------------------------------------------
__global__ __launch_bounds__(THREADS, 1)
void fused_attend_kernel(const float* __restrict__ X,
                         const float* __restrict__ W,
                         float* __restrict__ out_sem,
                         float* __restrict__ out_att,
                         float* __restrict__ out_part) {
    extern __shared__ float sm[];
    float* ATTs = sm + OFF_ATT;
    float* SEMs = sm + OFF_SEM;
    float* WSs  = sm + OFF_WS;
    float* XSs  = sm + OFF_XS;

    const int tid = threadIdx.x;
    const int tc = tid & 31;
    const int tr = tid >> 5;
    const int rowbase = blockIdx.x * BM;

    // load sem_att into smem
    for (int t = tid; t < LCLS * CDIM / 4; t += THREADS)
        *(float4*)&SEMs[t * 4] = *(const float4*)&g_sem[t * 4];
    __syncthreads();

    // ------------------- stage 3: attend over sem (L=10) -------------------
    #pragma unroll
    for (int i2 = 0; i2 < 2; ++i2) {
        float s3[4][10];
        #pragma unroll
        for (int k = 0; k < 4; ++k)
            #pragma unroll
            for (int l = 0; l < 10; ++l) s3[k][l] = 0.0f;

        #pragma unroll 4
        for (int u = 0; u < 16; ++u) {
            int cc = u * 32 + tc;
            float xv[4];
            #pragma unroll
            for (int k = 0; k < 4; ++k)
                xv[k] = X[(rowbase + tr * 8 + i2 * 4 + k) * CDIM + cc];
            #pragma unroll
            for (int l = 0; l < 10; ++l) {
                float sv = SEMs[l * CDIM + cc];
                #pragma unroll
                for (int k = 0; k < 4; ++k) s3[k][l] += xv[k] * sv;
            }
        }
        #pragma unroll
        for (int k = 0; k < 4; ++k) {
            #pragma unroll
            for (int l = 0; l < 10; ++l) s3[k][l] = wr_sum(s3[k][l]);
            float mx = s3[k][0];
            #pragma unroll
            for (int l = 1; l < 10; ++l) mx = fmaxf(mx, s3[k][l]);
            float se = 0.0f;
            #pragma unroll
            for (int l = 0; l < 10; ++l) { s3[k][l] = __expf(s3[k][l] - mx); se += s3[k][l]; }
            float inv = 1.0f / se;
            float l1 = 0.0f;
            #pragma unroll
            for (int l = 0; l < 10; ++l) {
                float a = s3[k][l] * inv;
                float t = a - SHRINK_L;
                float v = fmaxf(t, 0.0f) * a / (fabsf(t) + EPS_F);
                s3[k][l] = v; l1 += v;
            }
            float sc = 1.0f / fmaxf(l1, EPS_F);
            #pragma unroll
            for (int l = 0; l < 10; ++l) s3[k][l] *= sc;
            int rg = rowbase + tr * 8 + i2 * 4 + k;
            if (tc == 0) {
                #pragma unroll
                for (int l = 0; l < 10; ++l) out_att[rg * 10 + l] = s3[k][l];
            }
        }
        // readout with sem
        #pragma unroll 4
        for (int u = 0; u < 16; ++u) {
            int cc = u * 32 + tc;
            float acc[4] = {0.0f, 0.0f, 0.0f, 0.0f};
            #pragma unroll
            for (int l = 0; l < 10; ++l) {
                float sv = SEMs[l * CDIM + cc];
                #pragma unroll
                for (int k = 0; k < 4; ++k) acc[k] += s3[k][l] * sv;
            }
            #pragma unroll
            for (int k = 0; k < 4; ++k)
                out_sem[(rowbase + tr * 8 + i2 * 4 + k) * CDIM + cc] = acc[k];
        }
    }

    // ------------------- GEMM1: S[64,320] = X_tile @ W^T -------------------
    ull acc[8][5];
    #pragma unroll
    for (int i = 0; i < 8; ++i)
        #pragma unroll
        for (int j = 0; j < 5; ++j) acc[i][j] = 0ULL;

    for (int k0 = 0; k0 < CDIM; k0 += 32) {
        __syncthreads();
        // W tile, k-major in smem: WSs[kk][m], stride 322
        #pragma unroll
        for (int it = 0; it < 10; ++it) {
            int q = tid + it * THREADS;       // q < 2560
            int m = q >> 3, kq = q & 7;
            float4 w4 = *(const float4*)&W[m * CDIM + k0 + kq * 4];
            float* d = &WSs[(kq * 4) * WS_STRIDE + m];
            d[0] = w4.x; d[WS_STRIDE] = w4.y; d[2 * WS_STRIDE] = w4.z; d[3 * WS_STRIDE] = w4.w;
        }
        // X tile: XSs[r][kk], stride 36
        #pragma unroll
        for (int it = 0; it < 2; ++it) {
            int q = tid + it * THREADS;       // q < 512
            int r = q >> 3, kq = q & 7;
            float4 x4 = *(const float4*)&X[(rowbase + r) * CDIM + k0 + kq * 4];
            *(float4*)&XSs[r * XS_STRIDE + kq * 4] = x4;
        }
        __syncthreads();

        #pragma unroll 4
        for (int kk = 0; kk < 32; ++kk) {
            ull ap[8];
            #pragma unroll
            for (int i = 0; i < 8; ++i) {
                float a = XSs[(tr * 8 + i) * XS_STRIDE + kk];
                ap[i] = pack2(a, a);
            }
            #pragma unroll
            for (int j = 0; j < 5; ++j) {
                ull b = *(const ull*)&WSs[kk * WS_STRIDE + j * 64 + tc * 2];
                #pragma unroll
                for (int i = 0; i < 8; ++i) ffma2(acc[i][j], ap[i], b);
            }
        }
    }

    // --------- epilogue: softmax over 320, shrink, L1, to ATTs smem ---------
    #pragma unroll
    for (int i = 0; i < 8; ++i) {
        float sv[10];
        #pragma unroll
        for (int j = 0; j < 5; ++j) unpack2(acc[i][j], sv[2 * j], sv[2 * j + 1]);
        float mx = sv[0];
        #pragma unroll
        for (int x = 1; x < 10; ++x) mx = fmaxf(mx, sv[x]);
        mx = wr_max(mx);
        float se = 0.0f;
        #pragma unroll
        for (int x = 0; x < 10; ++x) { sv[x] = __expf(sv[x] - mx); se += sv[x]; }
        se = wr_sum(se);
        float inv = 1.0f / se;
        float l1 = 0.0f;
        #pragma unroll
        for (int x = 0; x < 10; ++x) {
            float a = sv[x] * inv;
            float t = a - SHRINK_L;
            float v = fmaxf(t, 0.0f) * a / (fabsf(t) + EPS_F);
            sv[x] = v; l1 += v;
        }
        l1 = wr_sum(l1);
        float sc = 1.0f / fmaxf(l1, EPS_F);
        #pragma unroll
        for (int j = 0; j < 5; ++j) {
            float2 p; p.x = sv[2 * j] * sc; p.y = sv[2 * j + 1] * sc;
            *(float2*)&ATTs[(tr * 8 + i) * MDIM + j * 64 + tc * 2] = p;
        }
    }

    // ------------- readout GEMM: O[64,512] = ATTs[64,320] @ W --------------
    #pragma unroll
    for (int ct = 0; ct < 2; ++ct) {
        ull acc2[8][4];
        #pragma unroll
        for (int i = 0; i < 8; ++i)
            #pragma unroll
            for (int j = 0; j < 4; ++j) acc2[i][j] = 0ULL;

        for (int k0 = 0; k0 < MDIM; k0 += 32) {
            __syncthreads();
            // W rows k0..k0+31, col half ct: WSs[kk][cc], stride 260
            #pragma unroll
            for (int it = 0; it < 8; ++it) {
                int q = tid + it * THREADS;   // q < 2048
                int kk = q >> 6, cc = (q & 63) << 2;
                *(float4*)&WSs[kk * WS2_STRIDE + cc] =
                    *(const float4*)&W[(k0 + kk) * CDIM + ct * 256 + cc];
            }
            __syncthreads();

            #pragma unroll 4
            for (int kk = 0; kk < 32; ++kk) {
                ull ap[8];
                #pragma unroll
                for (int i = 0; i < 8; ++i) {
                    float a = ATTs[(tr * 8 + i) * MDIM + k0 + kk];
                    ap[i] = pack2(a, a);
                }
                #pragma unroll
                for (int j = 0; j < 4; ++j) {
                    ull b = *(const ull*)&WSs[kk * WS2_STRIDE + j * 64 + tc * 2];
                    #pragma unroll
                    for (int i = 0; i < 8; ++i) ffma2(acc2[i][j], ap[i], b);
                }
            }
        }
        #pragma unroll
        for (int i = 0; i < 8; ++i) {
            int rg = rowbase + tr * 8 + i;
            #pragma unroll
            for (int j = 0; j < 4; ++j) {
                float lo, hi; unpack2(acc2[i][j], lo, hi);
                float2 p; p.x = lo; p.y = hi;
                *(float2*)&out_part[rg * CDIM + ct * 256 + j * 64 + tc * 2] = p;
            }
        }
    }
}

extern "C" void kernel_launch(void* const* d_in, const int* in_sizes, int n_in,
                              void* d_out, int out_size) {
    const float* X  = (const float*)d_in[0];
    const float* W  = (const float*)d_in[1];
    const float* wp = (const float*)d_in[2];
    const float* bp = (const float*)d_in[3];
    const float* wi = (const float*)d_in[4];
    const float* bi = (const float*)d_in[5];

    int N = in_sizes[0] / CDIM;   // 131072

    float* out       = (float*)d_out;
    float* out_sem   = out;                                   // [N, 512]
    float* out_att   = out + (size_t)N * CDIM;                // [N, 10]
    float* out_semm  = out_att + (size_t)N * LCLS;            // [10, 512]
    float* out_part  = out_semm + (size_t)LCLS * CDIM;        // [N, 512]

    sem_build_kernel<<<1, 512>>>(W, wp, bp, wi, bi, out_semm);

    int smem_bytes = SMEM_FLOATS * 4;
    cudaFuncSetAttribute(fused_attend_kernel,
                         cudaFuncAttributeMaxDynamicSharedMemorySize, smem_bytes);
    fused_attend_kernel<<<N / BM, THREADS, smem_bytes>>>(X, W, out_sem, out_att, out_part);
}

// round 12
// speedup vs baseline: 1.6391x; 1.0175x over previous
#include <cuda_runtime.h>
#include <cuda_bf16.h>

typedef unsigned int u32;
typedef unsigned long long u64;

#define CDIM 512
#define MDIM 320
#define LCLS 10
#define SHRINK_L 0.0025f
#define EPS_F 1e-12f
#define BM 64
#define THREADS 256
#define NMAX 131072

// ---- shared memory byte offsets ----
#define OFF_LOG 0              // 64*328*4 = 83968 (logits fp32)
#define OFF_SEM 0              // 20480 (phase A only, overlaps LOG)
#define OFF_T1  83968          // 64*328*2 = 41984 (att split1 bf16)
#define OFF_T2  125952         // 41984 (att split2 bf16)
#define OFF_INV 167936         // 64*4
#define SMEM_BYTES 168192
#define LSTR 328               // padded row stride (elements)

// ---- global scratch ----
__device__ u64  g_Xi[(size_t)NMAX * 256];        // {x1 bf16-pair, x2 bf16-pair} per 2 cols
__device__ uint4 g_B1[40 * 32 * 32];             // GEMM1 B frags [ntile][kstep][lane]
__device__ uint4 g_B2[64 * 20 * 32];             // GEMM2 B frags
__device__ float g_sem[LCLS * CDIM];

__device__ __forceinline__ float sigmoidf_(float x) { return 1.0f / (1.0f + __expf(-x)); }

__device__ __forceinline__ u32 pack_bf16(float lo, float hi) {
    __nv_bfloat162 h2 = __floats2bfloat162_rn(lo, hi);
    return *reinterpret_cast<u32*>(&h2);
}

__device__ __forceinline__ void hmma(float* c, u32 a0, u32 a1, u32 a2, u32 a3,
                                     u32 b0, u32 b1) {
    asm volatile(
        "mma.sync.aligned.m16n8k16.row.col.f32.bf16.bf16.f32 "
        "{%0,%1,%2,%3}, {%4,%5,%6,%7}, {%8,%9}, {%0,%1,%2,%3};"
        : "+f"(c[0]), "+f"(c[1]), "+f"(c[2]), "+f"(c[3])
        : "r"(a0), "r"(a1), "r"(a2), "r"(a3), "r"(b0), "r"(b1));
}

// ---------------------------------------------------------------------------
// Prologue 1: sem_att build (unchanged math)
// ---------------------------------------------------------------------------
__global__ void sem_build_kernel(const float* __restrict__ W,
                                 const float* __restrict__ wp,
                                 const float* __restrict__ bp,
                                 const float* __restrict__ wi,
                                 const float* __restrict__ bi,
                                 float* __restrict__ out_semmat) {
    int c = threadIdx.x;
    if (c >= CDIM) return;
    float wpl[16], bpl[4], wil[64], bil[8];
    #pragma unroll
    for (int i = 0; i < 16; ++i) wpl[i] = wp[i];
    #pragma unroll
    for (int i = 0; i < 4; ++i) bpl[i] = bp[i];
    #pragma unroll
    for (int i = 0; i < 64; ++i) wil[i] = wi[i];
    #pragma unroll
    for (int i = 0; i < 8; ++i) bil[i] = bi[i];

    for (int l = 0; l < LCLS; ++l) {
        float pt[8];
        #pragma unroll
        for (int t = 0; t < 8; ++t) {
            int n = l * 8 + t;
            float4 r4 = *(const float4*)(W + n * 2048 + c * 4);
            float rp[4] = {r4.x, r4.y, r4.z, r4.w};
            float acc = 0.0f;
            #pragma unroll
            for (int q = 0; q < 4; ++q) {
                float s = bpl[q];
                #pragma unroll
                for (int p = 0; p < 4; ++p) s += wpl[q * 4 + p] * rp[p];
                acc += sigmoidf_(s) * rp[q];
            }
            pt[t] = acc * 0.25f;
        }
        float acc2 = 0.0f;
        #pragma unroll
        for (int q = 0; q < 8; ++q) {
            float s = bil[q];
            #pragma unroll
            for (int t = 0; t < 8; ++t) s += wil[q * 8 + t] * pt[t];
            acc2 += sigmoidf_(s) * pt[q];
        }
        float v = acc2 * 0.125f;
        g_sem[l * CDIM + c] = v;
        out_semmat[l * CDIM + c] = v;
    }
}

// ---------------------------------------------------------------------------
// Prologue 2: split X into interleaved bf16 pairs
// ---------------------------------------------------------------------------
__global__ void xsplit_kernel(const float* __restrict__ X, int n4) {
    int i = blockIdx.x * 256 + threadIdx.x;
    if (i >= n4) return;
    float4 v = *(const float4*)(X + (size_t)i * 4);
    float vf[4] = {v.x, v.y, v.z, v.w};
    float h[4], l[4];
    #pragma unroll
    for (int e = 0; e < 4; ++e) {
        __nv_bfloat16 b = __float2bfloat16(vf[e]);
        h[e] = __bfloat162float(b);
        l[e] = vf[e] - h[e];
    }
    uint4 o;
    o.x = pack_bf16(h[0], h[1]);
    o.y = pack_bf16(l[0], l[1]);
    o.z = pack_bf16(h[2], h[3]);
    o.w = pack_bf16(l[2], l[3]);
    ((uint4*)g_Xi)[i] = o;
}

// ---------------------------------------------------------------------------
// Prologue 3: W fragments for GEMM1 (B = W^T, col n = memory index)
// frag: b0 = B[kb..kb+1][n], b1 = B[kb+8..kb+9][n]; B[k][n] = W[n][k]
// ---------------------------------------------------------------------------
__global__ void bfrag1_kernel(const float* __restrict__ W) {
    int idx = blockIdx.x * 256 + threadIdx.x;
    if (idx >= 40 * 32 * 32) return;
    int nt = idx >> 10, ks = (idx >> 5) & 31, l = idx & 31;
    int n = nt * 8 + (l >> 2);
    int kb = ks * 16 + 2 * (l & 3);
    float v[4] = { W[n * CDIM + kb], W[n * CDIM + kb + 1],
                   W[n * CDIM + kb + 8], W[n * CDIM + kb + 9] };
    float h[4], r[4];
    #pragma unroll
    for (int e = 0; e < 4; ++e) {
        __nv_bfloat16 b = __float2bfloat16(v[e]);
        h[e] = __bfloat162float(b);
        r[e] = v[e] - h[e];
    }
    uint4 o;
    o.x = pack_bf16(h[0], h[1]);
    o.y = pack_bf16(h[2], h[3]);
    o.z = pack_bf16(r[0], r[1]);
    o.w = pack_bf16(r[2], r[3]);
    g_B1[idx] = o;
}

// ---------------------------------------------------------------------------
// Prologue 4: W fragments for GEMM2 (B = W, n = output col, k = memory index)
// ---------------------------------------------------------------------------
__global__ void bfrag2_kernel(const float* __restrict__ W) {
    int idx = blockIdx.x * 256 + threadIdx.x;
    if (idx >= 64 * 20 * 32) return;
    int nt = idx / 640, rem = idx % 640;
    int ks = rem >> 5, l = rem & 31;
    int n = nt * 8 + (l >> 2);
    int kb = ks * 16 + 2 * (l & 3);
    float v[4] = { W[kb * CDIM + n], W[(kb + 1) * CDIM + n],
                   W[(kb + 8) * CDIM + n], W[(kb + 9) * CDIM + n] };
    float h[4], r[4];
    #pragma unroll
    for (int e = 0; e < 4; ++e) {
        __nv_bfloat16 b = __float2bfloat16(v[e]);
        h[e] = __bfloat162float(b);
        r[e] = v[e] - h[e];
    }
    uint4 o;
    o.x = pack_bf16(h[0], h[1]);
    o.y = pack_bf16(h[2], h[3]);
    o.z = pack_bf16(r[0], r[1]);
    o.w = pack_bf16(r[2], r[3]);
    g_B2[idx] = o;
}

// ---------------------------------------------------------------------------
// Main fused kernel: 64 rows per CTA, 256 threads
// ---------------------------------------------------------------------------
__global__ __launch_bounds__(THREADS, 1)
void fused_kernel(const float* __restrict__ X,
                  float* __restrict__ out_sem,
                  float* __restrict__ out_att,
                  float* __restrict__ out_part) {
    extern __shared__ char smem[];
    const int tid = threadIdx.x;
    const int wid = tid >> 5;
    const int lane = tid & 31;
    const int rowbase = blockIdx.x * BM;

    // =========================== Phase A: stage-3 ===========================
    {
        float* SEM = (float*)(smem + OFF_SEM);
        for (int i = tid; i < LCLS * CDIM / 4; i += THREADS)
            ((float4*)SEM)[i] = ((const float4*)g_sem)[i];
        __syncthreads();

        const int r = tid >> 2, h = tid & 3;
        const float4* xp = (const float4*)(X + (size_t)(rowbase + r) * CDIM);
        float s3[LCLS];
        #pragma unroll
        for (int l = 0; l < LCLS; ++l) s3[l] = 0.0f;

        #pragma unroll 4
        for (int u = 0; u < 32; ++u) {
            float4 xv = xp[u * 4 + h];
            int cc = u * 16 + h * 4;
            #pragma unroll
            for (int l = 0; l < LCLS; ++l) {
                float4 sv = *(const float4*)&SEM[l * CDIM + cc];
                s3[l] += xv.x * sv.x + xv.y * sv.y + xv.z * sv.z + xv.w * sv.w;
            }
        }
        #pragma unroll
        for (int l = 0; l < LCLS; ++l) {
            s3[l] += __shfl_xor_sync(0xffffffffu, s3[l], 1);
            s3[l] += __shfl_xor_sync(0xffffffffu, s3[l], 2);
        }

        float mx = s3[0];
        #pragma unroll
        for (int l = 1; l < LCLS; ++l) mx = fmaxf(mx, s3[l]);
        float se = 0.0f;
        #pragma unroll
        for (int l = 0; l < LCLS; ++l) { s3[l] = __expf(s3[l] - mx); se += s3[l]; }
        float inv = 1.0f / se;
        float l1 = 0.0f;
        #pragma unroll
        for (int l = 0; l < LCLS; ++l) {
            float a = s3[l] * inv;
            float t = a - SHRINK_L;
            float v = fmaxf(t, 0.0f) * a / (fabsf(t) + EPS_F);
            s3[l] = v; l1 += v;
        }
        float sc = 1.0f / fmaxf(l1, EPS_F);
        #pragma unroll
        for (int l = 0; l < LCLS; ++l) s3[l] *= sc;
        if (h == 0) {
            #pragma unroll
            for (int l = 0; l < LCLS; ++l)
                out_att[(size_t)(rowbase + r) * LCLS + l] = s3[l];
        }
        float4* op = (float4*)(out_sem + (size_t)(rowbase + r) * CDIM);
        #pragma unroll 4
        for (int u = 0; u < 32; ++u) {
            int cc = u * 16 + h * 4;
            float4 acc = make_float4(0.f, 0.f, 0.f, 0.f);
            #pragma unroll
            for (int l = 0; l < LCLS; ++l) {
                float4 sv = *(const float4*)&SEM[l * CDIM + cc];
                acc.x += s3[l] * sv.x; acc.y += s3[l] * sv.y;
                acc.z += s3[l] * sv.z; acc.w += s3[l] * sv.w;
            }
            op[u * 4 + h] = acc;
        }
        __syncthreads();   // SEM dead; logits region reused
    }

    const int wm = wid >> 1;          // 0..3 (M)
    const int wn = wid & 1;           // 0..1 (N)
    const int qr = lane >> 2;         // 0..7
    const int q  = lane & 3;          // 0..3

    // ====================== GEMM1: logits [64,320] ==========================
    {
        float acc[20][4];
        #pragma unroll
        for (int j = 0; j < 20; ++j)
            #pragma unroll
            for (int e = 0; e < 4; ++e) acc[j][e] = 0.0f;

        const u64* xr0 = g_Xi + (size_t)(rowbase + wm * 16 + qr) * 256;
        const u64* xr1 = xr0 + 8 * 256;
        const uint4* bbase = g_B1 + ((wn * 20) * 32) * 32 + lane;

        for (int ks = 0; ks < 32; ++ks) {
            int kp = ks * 8 + q;
            u64 A0 = xr0[kp], A1 = xr1[kp], A2 = xr0[kp + 4], A3 = xr1[kp + 4];
            u32 x1a0 = (u32)A0, x2a0 = (u32)(A0 >> 32);
            u32 x1a1 = (u32)A1, x2a1 = (u32)(A1 >> 32);
            u32 x1a2 = (u32)A2, x2a2 = (u32)(A2 >> 32);
            u32 x1a3 = (u32)A3, x2a3 = (u32)(A3 >> 32);
            const uint4* bp = bbase + ks * 32;
            #pragma unroll
            for (int j = 0; j < 20; ++j) {
                uint4 B = bp[j * 1024];
                hmma(acc[j], x1a0, x1a1, x1a2, x1a3, B.x, B.y);
                hmma(acc[j], x1a0, x1a1, x1a2, x1a3, B.z, B.w);
                hmma(acc[j], x2a0, x2a1, x2a2, x2a3, B.x, B.y);
            }
        }
        // store logits to smem
        float* LOG = (float*)(smem + OFF_LOG);
        int lr = wm * 16 + qr;
        #pragma unroll
        for (int j = 0; j < 20; ++j) {
            int col = wn * 160 + j * 8 + 2 * q;
            LOG[lr * LSTR + col]           = acc[j][0];
            LOG[lr * LSTR + col + 1]       = acc[j][1];
            LOG[(lr + 8) * LSTR + col]     = acc[j][2];
            LOG[(lr + 8) * LSTR + col + 1] = acc[j][3];
        }
    }
    __syncthreads();

    // ================ softmax-320 / shrink / bf16-split =====================
    {
        const int r = tid >> 2, h = tid & 3;
        float* Lr = (float*)(smem + OFF_LOG) + r * LSTR + h * 80;
        float m = -1e30f;
        #pragma unroll 8
        for (int i = 0; i < 80; ++i) m = fmaxf(m, Lr[i]);
        m = fmaxf(m, __shfl_xor_sync(0xffffffffu, m, 1));
        m = fmaxf(m, __shfl_xor_sync(0xffffffffu, m, 2));
        float s = 0.0f;
        #pragma unroll 8
        for (int i = 0; i < 80; ++i) { float e = __expf(Lr[i] - m); Lr[i] = e; s += e; }
        s += __shfl_xor_sync(0xffffffffu, s, 1);
        s += __shfl_xor_sync(0xffffffffu, s, 2);
        float invs = 1.0f / s;
        float l1 = 0.0f;
        u32* T1r = (u32*)(smem + OFF_T1 + (r * LSTR + h * 80) * 2);
        u32* T2r = (u32*)(smem + OFF_T2 + (r * LSTR + h * 80) * 2);
        #pragma unroll 4
        for (int i = 0; i < 40; ++i) {
            float a0 = Lr[2 * i] * invs;
            float a1 = Lr[2 * i + 1] * invs;
            float t0 = a0 - SHRINK_L, t1 = a1 - SHRINK_L;
            float v0 = fmaxf(t0, 0.0f) * a0 / (fabsf(t0) + EPS_F);
            float v1 = fmaxf(t1, 0.0f) * a1 / (fabsf(t1) + EPS_F);
            l1 += v0 + v1;
            __nv_bfloat16 b0 = __float2bfloat16(v0);
            __nv_bfloat16 b1 = __float2bfloat16(v1);
            float h0 = __bfloat162float(b0), h1 = __bfloat162float(b1);
            T1r[i] = pack_bf16(h0, h1);
            T2r[i] = pack_bf16(v0 - h0, v1 - h1);
        }
        l1 += __shfl_xor_sync(0xffffffffu, l1, 1);
        l1 += __shfl_xor_sync(0xffffffffu, l1, 2);
        if (h == 0)
            ((float*)(smem + OFF_INV))[r] = 1.0f / fmaxf(l1, EPS_F);
    }
    __syncthreads();

    // ================ GEMM2: out_part [64,512] (two halves) =================
    const int row = wm * 16 + qr;
    const float* INV = (const float*)(smem + OFF_INV);
    const float s0 = INV[row], s1 = INV[row + 8];

    #pragma unroll
    for (int hh = 0; hh < 2; ++hh) {
        float acc[16][4];
        #pragma unroll
        for (int j = 0; j < 16; ++j)
            #pragma unroll
            for (int e = 0; e < 4; ++e) acc[j][e] = 0.0f;

        const uint4* bbase = g_B2 + ((size_t)(hh * 32 + wn * 16) * 20) * 32 + lane;

        for (int ks = 0; ks < 20; ++ks) {
            int kb = ks * 16 + 2 * q;
            u32 a10 = *(const u32*)(smem + OFF_T1 + ((row)     * LSTR + kb) * 2);
            u32 a11 = *(const u32*)(smem + OFF_T1 + ((row + 8) * LSTR + kb) * 2);
            u32 a12 = *(const u32*)(smem + OFF_T1 + ((row)     * LSTR + kb + 8) * 2);
            u32 a13 = *(const u32*)(smem + OFF_T1 + ((row + 8) * LSTR + kb + 8) * 2);
            u32 a20 = *(const u32*)(smem + OFF_T2 + ((row)     * LSTR + kb) * 2);
            u32 a21 = *(const u32*)(smem + OFF_T2 + ((row + 8) * LSTR + kb) * 2);
            u32 a22 = *(const u32*)(smem + OFF_T2 + ((row)     * LSTR + kb + 8) * 2);
            u32 a23 = *(const u32*)(smem + OFF_T2 + ((row + 8) * LSTR + kb + 8) * 2);
            const uint4* bp = bbase + ks * 32;
            #pragma unroll
            for (int j = 0; j < 16; ++j) {
                uint4 B = bp[j * 640];
                hmma(acc[j], a10, a11, a12, a13, B.x, B.y);
                hmma(acc[j], a10, a11, a12, a13, B.z, B.w);
                hmma(acc[j], a20, a21, a22, a23, B.x, B.y);
            }
        }
        // epilogue: scale by 1/l1, write
        size_t gr = (size_t)(rowbase + row);
        #pragma unroll
        for (int j = 0; j < 16; ++j) {
            int col = hh * 256 + wn * 128 + j * 8 + 2 * q;
            float2 p0; p0.x = acc[j][0] * s0; p0.y = acc[j][1] * s0;
            float2 p1; p1.x = acc[j][2] * s1; p1.y = acc[j][3] * s1;
            *(float2*)(out_part + gr * CDIM + col)       = p0;
            *(float2*)(out_part + (gr + 8) * CDIM + col) = p1;
        }
    }
}

// ---------------------------------------------------------------------------
extern "C" void kernel_launch(void* const* d_in, const int* in_sizes, int n_in,
                              void* d_out, int out_size) {
    const float* X  = (const float*)d_in[0];
    const float* W  = (const float*)d_in[1];
    const float* wp = (const float*)d_in[2];
    const float* bp = (const float*)d_in[3];
    const float* wi = (const float*)d_in[4];
    const float* bi = (const float*)d_in[5];

    int N = in_sizes[0] / CDIM;   // 131072

    float* out      = (float*)d_out;
    float* out_sem  = out;                                   // [N, 512]
    float* out_att  = out + (size_t)N * CDIM;                // [N, 10]
    float* out_semm = out_att + (size_t)N * LCLS;            // [10, 512]
    float* out_part = out_semm + (size_t)LCLS * CDIM;        // [N, 512]

    sem_build_kernel<<<1, 512>>>(W, wp, bp, wi, bi, out_semm);
    int n4 = N * CDIM / 4;
    xsplit_kernel<<<(n4 + 255) / 256, 256>>>(X, n4);
    bfrag1_kernel<<<(40 * 32 * 32 + 255) / 256, 256>>>(W);
    bfrag2_kernel<<<(64 * 20 * 32 + 255) / 256, 256>>>(W);

    cudaFuncSetAttribute(fused_kernel,
                         cudaFuncAttributeMaxDynamicSharedMemorySize, SMEM_BYTES);
    fused_kernel<<<N / BM, THREADS, SMEM_BYTES>>>(X, out_sem, out_att, out_part);
}

// round 13
// speedup vs baseline: 2.2519x; 1.3739x over previous
#include <cuda_runtime.h>
#include <cuda_bf16.h>

typedef unsigned int u32;
typedef unsigned long long u64;

#define CDIM 512
#define MDIM 320
#define LCLS 10
#define SHRINK_L 0.0025f
#define EPS_F 1e-12f
#define BM 64
#define THREADS 256
#define NMAX 131072
#define LSTR 328

// ---- shared memory byte offsets ----
#define OFF_SEM  0          // 20480 (phase A only; overlaps T1)
#define OFF_T1   0          // 64*328*2 = 41984
#define OFF_T2   41984      // 41984  -> end 83968
#define OFF_BST  84992      // stage: GEMM1 2*40*32*16=40960 / GEMM2 2*32*32*16=32768
#define OFF_RED  125952     // 3 * 512B reduction buffers
#define SMEM_BYTES 127488

// ---- global scratch ----
__device__ u64  g_Xi[(size_t)NMAX * 256];   // {x1 pair, x2 pair} per 2 cols
__device__ uint4 g_B1[40 * 32 * 32];        // GEMM1 B frags [nt][ks][lane]
__device__ uint4 g_B2[64 * 20 * 32];        // GEMM2 B frags [nt][ks][lane]
__device__ float g_sem[LCLS * CDIM];

__device__ __forceinline__ float sigmoidf_(float x) { return 1.0f / (1.0f + __expf(-x)); }

__device__ __forceinline__ u32 pack_bf16(float lo, float hi) {
    __nv_bfloat162 h2 = __floats2bfloat162_rn(lo, hi);
    return *reinterpret_cast<u32*>(&h2);
}

__device__ __forceinline__ u32 smem_u32(const void* p) {
    u32 a;
    asm("{ .reg .u64 t; cvta.to.shared.u64 t, %1; cvt.u32.u64 %0, t; }" : "=r"(a) : "l"(p));
    return a;
}

__device__ __forceinline__ void cp16(u32 dst, const void* src) {
    asm volatile("cp.async.cg.shared.global [%0], [%1], 16;" :: "r"(dst), "l"(src) : "memory");
}
#define CP_COMMIT() asm volatile("cp.async.commit_group;" ::: "memory")
#define CP_WAIT0()  asm volatile("cp.async.wait_group 0;" ::: "memory")

__device__ __forceinline__ void hmma(float* c, u32 a0, u32 a1, u32 a2, u32 a3,
                                     u32 b0, u32 b1) {
    asm volatile(
        "mma.sync.aligned.m16n8k16.row.col.f32.bf16.bf16.f32 "
        "{%0,%1,%2,%3}, {%4,%5,%6,%7}, {%8,%9}, {%0,%1,%2,%3};"
        : "+f"(c[0]), "+f"(c[1]), "+f"(c[2]), "+f"(c[3])
        : "r"(a0), "r"(a1), "r"(a2), "r"(a3), "r"(b0), "r"(b1));
}

// ---------------------------------------------------------------------------
// Prologue 1: sem_att build
// ---------------------------------------------------------------------------
__global__ void sem_build_kernel(const float* __restrict__ W,
                                 const float* __restrict__ wp,
                                 const float* __restrict__ bp,
                                 const float* __restrict__ wi,
                                 const float* __restrict__ bi,
                                 float* __restrict__ out_semmat) {
    int c = threadIdx.x;
    if (c >= CDIM) return;
    float wpl[16], bpl[4], wil[64], bil[8];
    #pragma unroll
    for (int i = 0; i < 16; ++i) wpl[i] = wp[i];
    #pragma unroll
    for (int i = 0; i < 4; ++i) bpl[i] = bp[i];
    #pragma unroll
    for (int i = 0; i < 64; ++i) wil[i] = wi[i];
    #pragma unroll
    for (int i = 0; i < 8; ++i) bil[i] = bi[i];

    for (int l = 0; l < LCLS; ++l) {
        float pt[8];
        #pragma unroll
        for (int t = 0; t < 8; ++t) {
            int n = l * 8 + t;
            float4 r4 = *(const float4*)(W + n * 2048 + c * 4);
            float rp[4] = {r4.x, r4.y, r4.z, r4.w};
            float acc = 0.0f;
            #pragma unroll
            for (int q = 0; q < 4; ++q) {
                float s = bpl[q];
                #pragma unroll
                for (int p = 0; p < 4; ++p) s += wpl[q * 4 + p] * rp[p];
                acc += sigmoidf_(s) * rp[q];
            }
            pt[t] = acc * 0.25f;
        }
        float acc2 = 0.0f;
        #pragma unroll
        for (int q = 0; q < 8; ++q) {
            float s = bil[q];
            #pragma unroll
            for (int t = 0; t < 8; ++t) s += wil[q * 8 + t] * pt[t];
            acc2 += sigmoidf_(s) * pt[q];
        }
        float v = acc2 * 0.125f;
        g_sem[l * CDIM + c] = v;
        out_semmat[l * CDIM + c] = v;
    }
}

// ---------------------------------------------------------------------------
// Prologue 2: split X into interleaved bf16 pairs
// ---------------------------------------------------------------------------
__global__ void xsplit_kernel(const float* __restrict__ X, int n4) {
    int i = blockIdx.x * 256 + threadIdx.x;
    if (i >= n4) return;
    float4 v = *(const float4*)(X + (size_t)i * 4);
    float vf[4] = {v.x, v.y, v.z, v.w};
    float h[4], l[4];
    #pragma unroll
    for (int e = 0; e < 4; ++e) {
        __nv_bfloat16 b = __float2bfloat16(vf[e]);
        h[e] = __bfloat162float(b);
        l[e] = vf[e] - h[e];
    }
    uint4 o;
    o.x = pack_bf16(h[0], h[1]);
    o.y = pack_bf16(l[0], l[1]);
    o.z = pack_bf16(h[2], h[3]);
    o.w = pack_bf16(l[2], l[3]);
    ((uint4*)g_Xi)[i] = o;
}

// ---------------------------------------------------------------------------
// Prologue 3: W fragments for GEMM1 (B = W^T)
// ---------------------------------------------------------------------------
__global__ void bfrag1_kernel(const float* __restrict__ W) {
    int idx = blockIdx.x * 256 + threadIdx.x;
    if (idx >= 40 * 32 * 32) return;
    int nt = idx >> 10, ks = (idx >> 5) & 31, l = idx & 31;
    int n = nt * 8 + (l >> 2);
    int kb = ks * 16 + 2 * (l & 3);
    float v[4] = { W[n * CDIM + kb], W[n * CDIM + kb + 1],
                   W[n * CDIM + kb + 8], W[n * CDIM + kb + 9] };
    float h[4], r[4];
    #pragma unroll
    for (int e = 0; e < 4; ++e) {
        __nv_bfloat16 b = __float2bfloat16(v[e]);
        h[e] = __bfloat162float(b);
        r[e] = v[e] - h[e];
    }
    uint4 o;
    o.x = pack_bf16(h[0], h[1]);
    o.y = pack_bf16(h[2], h[3]);
    o.z = pack_bf16(r[0], r[1]);
    o.w = pack_bf16(r[2], r[3]);
    g_B1[idx] = o;
}

// ---------------------------------------------------------------------------
// Prologue 4: W fragments for GEMM2 (B = W)
// ---------------------------------------------------------------------------
__global__ void bfrag2_kernel(const float* __restrict__ W) {
    int idx = blockIdx.x * 256 + threadIdx.x;
    if (idx >= 64 * 20 * 32) return;
    int nt = idx / 640, rem = idx % 640;
    int ks = rem >> 5, l = rem & 31;
    int n = nt * 8 + (l >> 2);
    int kb = ks * 16 + 2 * (l & 3);
    float v[4] = { W[kb * CDIM + n], W[(kb + 1) * CDIM + n],
                   W[(kb + 8) * CDIM + n], W[(kb + 9) * CDIM + n] };
    float h[4], r[4];
    #pragma unroll
    for (int e = 0; e < 4; ++e) {
        __nv_bfloat16 b = __float2bfloat16(v[e]);
        h[e] = __bfloat162float(b);
        r[e] = v[e] - h[e];
    }
    uint4 o;
    o.x = pack_bf16(h[0], h[1]);
    o.y = pack_bf16(h[2], h[3]);
    o.z = pack_bf16(r[0], r[1]);
    o.w = pack_bf16(r[2], r[3]);
    g_B2[idx] = o;
}

// ---------------------------------------------------------------------------
// Main fused kernel
// ---------------------------------------------------------------------------
__global__ __launch_bounds__(THREADS, 1)
void fused_kernel(const float* __restrict__ X,
                  float* __restrict__ out_sem,
                  float* __restrict__ out_att,
                  float* __restrict__ out_part) {
    extern __shared__ char smem[];
    const u32 sb = smem_u32(smem);
    const int tid = threadIdx.x;
    const int wid = tid >> 5;
    const int lane = tid & 31;
    const int rowbase = blockIdx.x * BM;

    // =========================== Phase A: stage-3 ===========================
    {
        float* SEM = (float*)(smem + OFF_SEM);
        for (int i = tid; i < LCLS * CDIM / 4; i += THREADS)
            ((float4*)SEM)[i] = ((const float4*)g_sem)[i];
        __syncthreads();

        const int r = tid >> 2, h = tid & 3;
        const float4* xp = (const float4*)(X + (size_t)(rowbase + r) * CDIM);
        float s3[LCLS];
        #pragma unroll
        for (int l = 0; l < LCLS; ++l) s3[l] = 0.0f;

        #pragma unroll 4
        for (int u = 0; u < 32; ++u) {
            float4 xv = xp[u * 4 + h];
            int cc = u * 16 + h * 4;
            #pragma unroll
            for (int l = 0; l < LCLS; ++l) {
                float4 sv = *(const float4*)&SEM[l * CDIM + cc];
                s3[l] += xv.x * sv.x + xv.y * sv.y + xv.z * sv.z + xv.w * sv.w;
            }
        }
        #pragma unroll
        for (int l = 0; l < LCLS; ++l) {
            s3[l] += __shfl_xor_sync(0xffffffffu, s3[l], 1);
            s3[l] += __shfl_xor_sync(0xffffffffu, s3[l], 2);
        }

        float mx = s3[0];
        #pragma unroll
        for (int l = 1; l < LCLS; ++l) mx = fmaxf(mx, s3[l]);
        float se = 0.0f;
        #pragma unroll
        for (int l = 0; l < LCLS; ++l) { s3[l] = __expf(s3[l] - mx); se += s3[l]; }
        float inv = 1.0f / se;
        float l1 = 0.0f;
        #pragma unroll
        for (int l = 0; l < LCLS; ++l) {
            float a = s3[l] * inv;
            float t = a - SHRINK_L;
            float v = fmaxf(t, 0.0f) * a / (fabsf(t) + EPS_F);
            s3[l] = v; l1 += v;
        }
        float sc = 1.0f / fmaxf(l1, EPS_F);
        #pragma unroll
        for (int l = 0; l < LCLS; ++l) s3[l] *= sc;
        if (h == 0) {
            #pragma unroll
            for (int l = 0; l < LCLS; ++l)
                out_att[(size_t)(rowbase + r) * LCLS + l] = s3[l];
        }
        float4* op = (float4*)(out_sem + (size_t)(rowbase + r) * CDIM);
        #pragma unroll 4
        for (int u = 0; u < 32; ++u) {
            int cc = u * 16 + h * 4;
            float4 acc = make_float4(0.f, 0.f, 0.f, 0.f);
            #pragma unroll
            for (int l = 0; l < LCLS; ++l) {
                float4 sv = *(const float4*)&SEM[l * CDIM + cc];
                acc.x += s3[l] * sv.x; acc.y += s3[l] * sv.y;
                acc.z += s3[l] * sv.z; acc.w += s3[l] * sv.w;
            }
            op[u * 4 + h] = acc;
        }
        __syncthreads();
    }

    const int wm = wid >> 1;          // 0..3 (M tile)
    const int wn = wid & 1;           // 0..1 (N half)
    const int qr = lane >> 2;         // 0..7
    const int q  = lane & 3;          // 0..3
    const int row = wm * 16 + qr;

    // ====================== GEMM1: logits [64,320] ==========================
    float acc[20][4];
    {
        #pragma unroll
        for (int j = 0; j < 20; ++j)
            #pragma unroll
            for (int e = 0; e < 4; ++e) acc[j][e] = 0.0f;

        const u64* xr0 = g_Xi + (size_t)(rowbase + row) * 256;
        const u64* xr1 = xr0 + 8 * 256;

        const int f_nt = tid >> 5;         // fill: nt for it=0 ... +8 per it
        const int f_l  = lane;
        // prologue fill ks=0 -> buf 0
        #pragma unroll
        for (int it = 0; it < 5; ++it) {
            int i = tid + it * 256;
            int nt = i >> 5;
            cp16(sb + OFF_BST + (u32)i * 16, &g_B1[nt * 1024 + 0 * 32 + (i & 31)]);
        }
        CP_COMMIT(); CP_WAIT0();
        __syncthreads();

        for (int ks = 0; ks < 32; ++ks) {
            int cbuf = ks & 1;
            if (ks < 31) {
                int ks2 = ks + 1;
                #pragma unroll
                for (int it = 0; it < 5; ++it) {
                    int i = tid + it * 256;
                    int nt = i >> 5;
                    cp16(sb + OFF_BST + (u32)((cbuf ^ 1) * 1280 + i) * 16,
                         &g_B1[nt * 1024 + ks2 * 32 + (i & 31)]);
                }
                CP_COMMIT();
            }
            int kp = ks * 8 + q;
            u64 A0 = xr0[kp], A1 = xr1[kp], A2 = xr0[kp + 4], A3 = xr1[kp + 4];
            u32 x1a0 = (u32)A0, x2a0 = (u32)(A0 >> 32);
            u32 x1a1 = (u32)A1, x2a1 = (u32)(A1 >> 32);
            u32 x1a2 = (u32)A2, x2a2 = (u32)(A2 >> 32);
            u32 x1a3 = (u32)A3, x2a3 = (u32)(A3 >> 32);
            const uint4* bp = (const uint4*)(smem + OFF_BST) + cbuf * 1280 + wn * 640 + lane;
            #pragma unroll
            for (int j = 0; j < 20; ++j) {
                uint4 B = bp[j * 32];
                hmma(acc[j], x1a0, x1a1, x1a2, x1a3, B.x, B.y);
                hmma(acc[j], x1a0, x1a1, x1a2, x1a3, B.z, B.w);
                hmma(acc[j], x2a0, x2a1, x2a2, x2a3, B.x, B.y);
                hmma(acc[j], x2a0, x2a1, x2a2, x2a3, B.z, B.w);
            }
            CP_WAIT0();
            __syncthreads();
        }
        (void)f_nt; (void)f_l;
    }

    // ============ softmax-320 / shrink / bf16-split (from regs) =============
    float* RED0 = (float*)(smem + OFF_RED);          // [2][64] max
    float* RED1 = RED0 + 128;                         // [2][64] expsum
    float* RED2 = RED1 + 128;                         // [2][64] l1
    {
        // round 1: row max
        float m0 = -1e30f, m1 = -1e30f;
        #pragma unroll
        for (int j = 0; j < 20; ++j) {
            m0 = fmaxf(m0, fmaxf(acc[j][0], acc[j][1]));
            m1 = fmaxf(m1, fmaxf(acc[j][2], acc[j][3]));
        }
        m0 = fmaxf(m0, __shfl_xor_sync(0xffffffffu, m0, 1));
        m0 = fmaxf(m0, __shfl_xor_sync(0xffffffffu, m0, 2));
        m1 = fmaxf(m1, __shfl_xor_sync(0xffffffffu, m1, 1));
        m1 = fmaxf(m1, __shfl_xor_sync(0xffffffffu, m1, 2));
        if (q == 0) { RED0[wn * 64 + row] = m0; RED0[wn * 64 + row + 8] = m1; }
        __syncthreads();
        float M0 = fmaxf(RED0[row],     RED0[64 + row]);
        float M1 = fmaxf(RED0[row + 8], RED0[64 + row + 8]);

        // round 2: exp + expsum
        float s0 = 0.0f, s1 = 0.0f;
        #pragma unroll
        for (int j = 0; j < 20; ++j) {
            acc[j][0] = __expf(acc[j][0] - M0);
            acc[j][1] = __expf(acc[j][1] - M0);
            acc[j][2] = __expf(acc[j][2] - M1);
            acc[j][3] = __expf(acc[j][3] - M1);
            s0 += acc[j][0] + acc[j][1];
            s1 += acc[j][2] + acc[j][3];
        }
        s0 += __shfl_xor_sync(0xffffffffu, s0, 1);
        s0 += __shfl_xor_sync(0xffffffffu, s0, 2);
        s1 += __shfl_xor_sync(0xffffffffu, s1, 1);
        s1 += __shfl_xor_sync(0xffffffffu, s1, 2);
        if (q == 0) { RED1[wn * 64 + row] = s0; RED1[wn * 64 + row + 8] = s1; }
        __syncthreads();
        float inv0 = 1.0f / (RED1[row]     + RED1[64 + row]);
        float inv1 = 1.0f / (RED1[row + 8] + RED1[64 + row + 8]);

        // round 3: shrink, l1, store T1/T2 frags
        float l10 = 0.0f, l11 = 0.0f;
        u32* T1 = (u32*)(smem + OFF_T1);
        u32* T2 = (u32*)(smem + OFF_T2);
        #pragma unroll
        for (int j = 0; j < 20; ++j) {
            int col = wn * 160 + j * 8 + 2 * q;
            float a0 = acc[j][0] * inv0, a1 = acc[j][1] * inv0;
            float a2 = acc[j][2] * inv1, a3 = acc[j][3] * inv1;
            float t0 = a0 - SHRINK_L, t1 = a1 - SHRINK_L;
            float t2 = a2 - SHRINK_L, t3 = a3 - SHRINK_L;
            float v0 = fmaxf(t0, 0.0f) * a0 / (fabsf(t0) + EPS_F);
            float v1 = fmaxf(t1, 0.0f) * a1 / (fabsf(t1) + EPS_F);
            float v2 = fmaxf(t2, 0.0f) * a2 / (fabsf(t2) + EPS_F);
            float v3 = fmaxf(t3, 0.0f) * a3 / (fabsf(t3) + EPS_F);
            l10 += v0 + v1; l11 += v2 + v3;
            __nv_bfloat16 b0 = __float2bfloat16(v0), b1 = __float2bfloat16(v1);
            __nv_bfloat16 b2 = __float2bfloat16(v2), b3 = __float2bfloat16(v3);
            float h0 = __bfloat162float(b0), h1 = __bfloat162float(b1);
            float h2 = __bfloat162float(b2), h3 = __bfloat162float(b3);
            int w0 = (row * LSTR + col) >> 1;
            int w1 = ((row + 8) * LSTR + col) >> 1;
            T1[w0] = pack_bf16(h0, h1);
            T1[w1] = pack_bf16(h2, h3);
            T2[w0] = pack_bf16(v0 - h0, v1 - h1);
            T2[w1] = pack_bf16(v2 - h2, v3 - h3);
        }
        l10 += __shfl_xor_sync(0xffffffffu, l10, 1);
        l10 += __shfl_xor_sync(0xffffffffu, l10, 2);
        l11 += __shfl_xor_sync(0xffffffffu, l11, 1);
        l11 += __shfl_xor_sync(0xffffffffu, l11, 2);
        if (q == 0) { RED2[wn * 64 + row] = l10; RED2[wn * 64 + row + 8] = l11; }
        __syncthreads();
    }
    const float sc0 = 1.0f / fmaxf(RED2[row]     + RED2[64 + row],     EPS_F);
    const float sc1 = 1.0f / fmaxf(RED2[row + 8] + RED2[64 + row + 8], EPS_F);

    // ================ GEMM2: out_part [64,512], flattened ===================
    {
        // prologue fill step 0 (hh=0, ks=0) -> buf 0
        #pragma unroll
        for (int it = 0; it < 4; ++it) {
            int i = tid + it * 256;
            int jj = i >> 5;
            cp16(sb + OFF_BST + (u32)i * 16, &g_B2[jj * 640 + 0 * 32 + (i & 31)]);
        }
        CP_COMMIT(); CP_WAIT0();
        __syncthreads();

        float acc2[16][4];
        for (int s = 0; s < 40; ++s) {
            int hh = s / 20, ks = s % 20;
            int cbuf = s & 1;
            if (ks == 0) {
                #pragma unroll
                for (int j = 0; j < 16; ++j)
                    #pragma unroll
                    for (int e = 0; e < 4; ++e) acc2[j][e] = 0.0f;
            }
            if (s < 39) {
                int s2 = s + 1;
                int hh2 = s2 / 20, ks2 = s2 % 20;
                #pragma unroll
                for (int it = 0; it < 4; ++it) {
                    int i = tid + it * 256;
                    int jj = i >> 5;
                    cp16(sb + OFF_BST + (u32)((cbuf ^ 1) * 1024 + i) * 16,
                         &g_B2[(hh2 * 32 + jj) * 640 + ks2 * 32 + (i & 31)]);
                }
                CP_COMMIT();
            }
            int kb = ks * 16 + 2 * q;
            const u32* T1 = (const u32*)(smem + OFF_T1);
            const u32* T2 = (const u32*)(smem + OFF_T2);
            u32 a10 = T1[(row * LSTR + kb) >> 1];
            u32 a11 = T1[((row + 8) * LSTR + kb) >> 1];
            u32 a12 = T1[(row * LSTR + kb + 8) >> 1];
            u32 a13 = T1[((row + 8) * LSTR + kb + 8) >> 1];
            u32 a20 = T2[(row * LSTR + kb) >> 1];
            u32 a21 = T2[((row + 8) * LSTR + kb) >> 1];
            u32 a22 = T2[(row * LSTR + kb + 8) >> 1];
            u32 a23 = T2[((row + 8) * LSTR + kb + 8) >> 1];
            const uint4* bp = (const uint4*)(smem + OFF_BST) + cbuf * 1024 + wn * 512 + lane;
            #pragma unroll
            for (int j = 0; j < 16; ++j) {
                uint4 B = bp[j * 32];
                hmma(acc2[j], a10, a11, a12, a13, B.x, B.y);
                hmma(acc2[j], a10, a11, a12, a13, B.z, B.w);
                hmma(acc2[j], a20, a21, a22, a23, B.x, B.y);
            }
            CP_WAIT0();
            __syncthreads();

            if (ks == 19) {
                size_t gr = (size_t)(rowbase + row);
                #pragma unroll
                for (int j = 0; j < 16; ++j) {
                    int col = hh * 256 + wn * 128 + j * 8 + 2 * q;
                    float2 p0; p0.x = acc2[j][0] * sc0; p0.y = acc2[j][1] * sc0;
                    float2 p1; p1.x = acc2[j][2] * sc1; p1.y = acc2[j][3] * sc1;
                    *(float2*)(out_part + gr * CDIM + col)       = p0;
                    *(float2*)(out_part + (gr + 8) * CDIM + col) = p1;
                }
            }
        }
    }
}

// ---------------------------------------------------------------------------
extern "C" void kernel_launch(void* const* d_in, const int* in_sizes, int n_in,
                              void* d_out, int out_size) {
    const float* X  = (const float*)d_in[0];
    const float* W  = (const float*)d_in[1];
    const float* wp = (const float*)d_in[2];
    const float* bp = (const float*)d_in[3];
    const float* wi = (const float*)d_in[4];
    const float* bi = (const float*)d_in[5];

    int N = in_sizes[0] / CDIM;   // 131072

    float* out      = (float*)d_out;
    float* out_sem  = out;                                   // [N, 512]
    float* out_att  = out + (size_t)N * CDIM;                // [N, 10]
    float* out_semm = out_att + (size_t)N * LCLS;            // [10, 512]
    float* out_part = out_semm + (size_t)LCLS * CDIM;        // [N, 512]

    sem_build_kernel<<<1, 512>>>(W, wp, bp, wi, bi, out_semm);
    int n4 = N * CDIM / 4;
    xsplit_kernel<<<(n4 + 255) / 256, 256>>>(X, n4);
    bfrag1_kernel<<<(40 * 32 * 32 + 255) / 256, 256>>>(W);
    bfrag2_kernel<<<(64 * 20 * 32 + 255) / 256, 256>>>(W);

    cudaFuncSetAttribute(fused_kernel,
                         cudaFuncAttributeMaxDynamicSharedMemorySize, SMEM_BYTES);
    fused_kernel<<<N / BM, THREADS, SMEM_BYTES>>>(X, out_sem, out_att, out_part);
}

// round 14
// speedup vs baseline: 2.5146x; 1.1167x over previous
#include <cuda_runtime.h>
#include <cuda_bf16.h>

typedef unsigned int u32;
typedef unsigned long long u64;

#define CDIM 512
#define MDIM 320
#define LCLS 10
#define SHRINK_L 0.0025f
#define EPS_F 1e-12f
#define BM 64
#define THREADS 256
#define NMAX 131072
#define LSTR 328

// ---- shared memory byte offsets ----
#define OFF_SEM  0          // 20480 (phase A only; overlaps T1)
#define OFF_T1   0          // 64*328*2 = 41984
#define OFF_T2   41984      // 41984  -> end 83968
#define OFF_BST  84992      // 3-stage ring: GEMM1 3*20480=61440 / GEMM2 3*16384=49152
#define OFF_RED  146432     // 3 * 512B reduction buffers
#define SMEM_BYTES 147968
#define ST1 20480
#define ST2 16384

// ---- global scratch ----
__device__ u64  g_Xi[(size_t)NMAX * 256];   // {x1 pair, x2 pair} per 2 cols
__device__ uint4 g_B1[40 * 32 * 32];        // GEMM1 B frags [nt][ks][lane]
__device__ uint4 g_B2[64 * 20 * 32];        // GEMM2 B frags [nt][ks][lane]
__device__ float g_sem[LCLS * CDIM];

__device__ __forceinline__ float sigmoidf_(float x) { return 1.0f / (1.0f + __expf(-x)); }

__device__ __forceinline__ u32 pack_bf16(float lo, float hi) {
    __nv_bfloat162 h2 = __floats2bfloat162_rn(lo, hi);
    return *reinterpret_cast<u32*>(&h2);
}

__device__ __forceinline__ u32 smem_u32(const void* p) {
    u32 a;
    asm("{ .reg .u64 t; cvta.to.shared.u64 t, %1; cvt.u32.u64 %0, t; }" : "=r"(a) : "l"(p));
    return a;
}

__device__ __forceinline__ void cp16(u32 dst, const void* src) {
    asm volatile("cp.async.cg.shared.global [%0], [%1], 16;" :: "r"(dst), "l"(src) : "memory");
}
#define CP_COMMIT() asm volatile("cp.async.commit_group;" ::: "memory")
#define CP_WAIT0()  asm volatile("cp.async.wait_group 0;" ::: "memory")
#define CP_WAIT1()  asm volatile("cp.async.wait_group 1;" ::: "memory")

__device__ __forceinline__ void hmma(float* c, u32 a0, u32 a1, u32 a2, u32 a3,
                                     u32 b0, u32 b1) {
    asm volatile(
        "mma.sync.aligned.m16n8k16.row.col.f32.bf16.bf16.f32 "
        "{%0,%1,%2,%3}, {%4,%5,%6,%7}, {%8,%9}, {%0,%1,%2,%3};"
        : "+f"(c[0]), "+f"(c[1]), "+f"(c[2]), "+f"(c[3])
        : "r"(a0), "r"(a1), "r"(a2), "r"(a3), "r"(b0), "r"(b1));
}

// ---------------------------------------------------------------------------
// Prologue 1: sem_att build
// ---------------------------------------------------------------------------
__global__ void sem_build_kernel(const float* __restrict__ W,
                                 const float* __restrict__ wp,
                                 const float* __restrict__ bp,
                                 const float* __restrict__ wi,
                                 const float* __restrict__ bi,
                                 float* __restrict__ out_semmat) {
    int c = threadIdx.x;
    if (c >= CDIM) return;
    float wpl[16], bpl[4], wil[64], bil[8];
    #pragma unroll
    for (int i = 0; i < 16; ++i) wpl[i] = wp[i];
    #pragma unroll
    for (int i = 0; i < 4; ++i) bpl[i] = bp[i];
    #pragma unroll
    for (int i = 0; i < 64; ++i) wil[i] = wi[i];
    #pragma unroll
    for (int i = 0; i < 8; ++i) bil[i] = bi[i];

    for (int l = 0; l < LCLS; ++l) {
        float pt[8];
        #pragma unroll
        for (int t = 0; t < 8; ++t) {
            int n = l * 8 + t;
            float4 r4 = *(const float4*)(W + n * 2048 + c * 4);
            float rp[4] = {r4.x, r4.y, r4.z, r4.w};
            float acc = 0.0f;
            #pragma unroll
            for (int q = 0; q < 4; ++q) {
                float s = bpl[q];
                #pragma unroll
                for (int p = 0; p < 4; ++p) s += wpl[q * 4 + p] * rp[p];
                acc += sigmoidf_(s) * rp[q];
            }
            pt[t] = acc * 0.25f;
        }
        float acc2 = 0.0f;
        #pragma unroll
        for (int q = 0; q < 8; ++q) {
            float s = bil[q];
            #pragma unroll
            for (int t = 0; t < 8; ++t) s += wil[q * 8 + t] * pt[t];
            acc2 += sigmoidf_(s) * pt[q];
        }
        float v = acc2 * 0.125f;
        g_sem[l * CDIM + c] = v;
        out_semmat[l * CDIM + c] = v;
    }
}

// ---------------------------------------------------------------------------
// Prologue 2: split X into interleaved bf16 pairs
// ---------------------------------------------------------------------------
__global__ void xsplit_kernel(const float* __restrict__ X, int n4) {
    int i = blockIdx.x * 256 + threadIdx.x;
    if (i >= n4) return;
    float4 v = *(const float4*)(X + (size_t)i * 4);
    float vf[4] = {v.x, v.y, v.z, v.w};
    float h[4], l[4];
    #pragma unroll
    for (int e = 0; e < 4; ++e) {
        __nv_bfloat16 b = __float2bfloat16(vf[e]);
        h[e] = __bfloat162float(b);
        l[e] = vf[e] - h[e];
    }
    uint4 o;
    o.x = pack_bf16(h[0], h[1]);
    o.y = pack_bf16(l[0], l[1]);
    o.z = pack_bf16(h[2], h[3]);
    o.w = pack_bf16(l[2], l[3]);
    ((uint4*)g_Xi)[i] = o;
}

// ---------------------------------------------------------------------------
// Prologue 3: W fragments for GEMM1 (B = W^T)
// ---------------------------------------------------------------------------
__global__ void bfrag1_kernel(const float* __restrict__ W) {
    int idx = blockIdx.x * 256 + threadIdx.x;
    if (idx >= 40 * 32 * 32) return;
    int nt = idx >> 10, ks = (idx >> 5) & 31, l = idx & 31;
    int n = nt * 8 + (l >> 2);
    int kb = ks * 16 + 2 * (l & 3);
    float v[4] = { W[n * CDIM + kb], W[n * CDIM + kb + 1],
                   W[n * CDIM + kb + 8], W[n * CDIM + kb + 9] };
    float h[4], r[4];
    #pragma unroll
    for (int e = 0; e < 4; ++e) {
        __nv_bfloat16 b = __float2bfloat16(v[e]);
        h[e] = __bfloat162float(b);
        r[e] = v[e] - h[e];
    }
    uint4 o;
    o.x = pack_bf16(h[0], h[1]);
    o.y = pack_bf16(h[2], h[3]);
    o.z = pack_bf16(r[0], r[1]);
    o.w = pack_bf16(r[2], r[3]);
    g_B1[idx] = o;
}

// ---------------------------------------------------------------------------
// Prologue 4: W fragments for GEMM2 (B = W)
// ---------------------------------------------------------------------------
__global__ void bfrag2_kernel(const float* __restrict__ W) {
    int idx = blockIdx.x * 256 + threadIdx.x;
    if (idx >= 64 * 20 * 32) return;
    int nt = idx / 640, rem = idx % 640;
    int ks = rem >> 5, l = rem & 31;
    int n = nt * 8 + (l >> 2);
    int kb = ks * 16 + 2 * (l & 3);
    float v[4] = { W[kb * CDIM + n], W[(kb + 1) * CDIM + n],
                   W[(kb + 8) * CDIM + n], W[(kb + 9) * CDIM + n] };
    float h[4], r[4];
    #pragma unroll
    for (int e = 0; e < 4; ++e) {
        __nv_bfloat16 b = __float2bfloat16(v[e]);
        h[e] = __bfloat162float(b);
        r[e] = v[e] - h[e];
    }
    uint4 o;
    o.x = pack_bf16(h[0], h[1]);
    o.y = pack_bf16(h[2], h[3]);
    o.z = pack_bf16(r[0], r[1]);
    o.w = pack_bf16(r[2], r[3]);
    g_B2[idx] = o;
}

// ---------------------------------------------------------------------------
// Main fused kernel
// ---------------------------------------------------------------------------
__global__ __launch_bounds__(THREADS, 1)
void fused_kernel(const float* __restrict__ X,
                  float* __restrict__ out_sem,
                  float* __restrict__ out_att,
                  float* __restrict__ out_part) {
    extern __shared__ char smem[];
    const u32 sb = smem_u32(smem);
    const int tid = threadIdx.x;
    const int wid = tid >> 5;
    const int lane = tid & 31;
    const int rowbase = blockIdx.x * BM;

    // =========================== Phase A: stage-3 ===========================
    {
        float* SEM = (float*)(smem + OFF_SEM);
        for (int i = tid; i < LCLS * CDIM / 4; i += THREADS)
            ((float4*)SEM)[i] = ((const float4*)g_sem)[i];
        __syncthreads();

        const int r = tid >> 2, h = tid & 3;
        const float4* xp = (const float4*)(X + (size_t)(rowbase + r) * CDIM);
        float s3[LCLS];
        #pragma unroll
        for (int l = 0; l < LCLS; ++l) s3[l] = 0.0f;

        #pragma unroll 4
        for (int u = 0; u < 32; ++u) {
            float4 xv = xp[u * 4 + h];
            int cc = u * 16 + h * 4;
            #pragma unroll
            for (int l = 0; l < LCLS; ++l) {
                float4 sv = *(const float4*)&SEM[l * CDIM + cc];
                s3[l] += xv.x * sv.x + xv.y * sv.y + xv.z * sv.z + xv.w * sv.w;
            }
        }
        #pragma unroll
        for (int l = 0; l < LCLS; ++l) {
            s3[l] += __shfl_xor_sync(0xffffffffu, s3[l], 1);
            s3[l] += __shfl_xor_sync(0xffffffffu, s3[l], 2);
        }

        float mx = s3[0];
        #pragma unroll
        for (int l = 1; l < LCLS; ++l) mx = fmaxf(mx, s3[l]);
        float se = 0.0f;
        #pragma unroll
        for (int l = 0; l < LCLS; ++l) { s3[l] = __expf(s3[l] - mx); se += s3[l]; }
        float inv = 1.0f / se;
        float l1 = 0.0f;
        #pragma unroll
        for (int l = 0; l < LCLS; ++l) {
            float a = s3[l] * inv;
            float t = a - SHRINK_L;
            float v = fmaxf(t, 0.0f) * a / (fabsf(t) + EPS_F);
            s3[l] = v; l1 += v;
        }
        float sc = 1.0f / fmaxf(l1, EPS_F);
        #pragma unroll
        for (int l = 0; l < LCLS; ++l) s3[l] *= sc;
        if (h == 0) {
            #pragma unroll
            for (int l = 0; l < LCLS; ++l)
                out_att[(size_t)(rowbase + r) * LCLS + l] = s3[l];
        }
        float4* op = (float4*)(out_sem + (size_t)(rowbase + r) * CDIM);
        #pragma unroll 4
        for (int u = 0; u < 32; ++u) {
            int cc = u * 16 + h * 4;
            float4 acc = make_float4(0.f, 0.f, 0.f, 0.f);
            #pragma unroll
            for (int l = 0; l < LCLS; ++l) {
                float4 sv = *(const float4*)&SEM[l * CDIM + cc];
                acc.x += s3[l] * sv.x; acc.y += s3[l] * sv.y;
                acc.z += s3[l] * sv.z; acc.w += s3[l] * sv.w;
            }
            op[u * 4 + h] = acc;
        }
        __syncthreads();
    }

    const int wm = wid >> 1;          // 0..3 (M tile)
    const int wn = wid & 1;           // 0..1 (N half)
    const int qr = lane >> 2;         // 0..7
    const int q  = lane & 3;          // 0..3
    const int row = wm * 16 + qr;

    // ====================== GEMM1: logits [64,320] ==========================
    float acc[20][4];
    {
        #pragma unroll
        for (int j = 0; j < 20; ++j)
            #pragma unroll
            for (int e = 0; e < 4; ++e) acc[j][e] = 0.0f;

        const u64* xr0 = g_Xi + (size_t)(rowbase + row) * 256;
        const u64* xr1 = xr0 + 8 * 256;

        // prologue: fill stages 0,1 (ks=0,1)
        #pragma unroll
        for (int s = 0; s < 2; ++s) {
            #pragma unroll
            for (int it = 0; it < 5; ++it) {
                int i = tid + it * 256;
                int nt = i >> 5;
                cp16(sb + OFF_BST + (u32)(s * ST1 + i * 16),
                     &g_B1[nt * 1024 + s * 32 + (i & 31)]);
            }
            CP_COMMIT();
        }
        // prefetch A for ks=0
        u64 nA0 = xr0[q], nA1 = xr1[q], nA2 = xr0[q + 4], nA3 = xr1[q + 4];

        for (int ks = 0; ks < 32; ++ks) {
            if (ks >= 30) { CP_WAIT0(); } else { CP_WAIT1(); }
            __syncthreads();
            if (ks + 2 < 32) {
                int ks2 = ks + 2, stg2 = ks2 % 3;
                #pragma unroll
                for (int it = 0; it < 5; ++it) {
                    int i = tid + it * 256;
                    int nt = i >> 5;
                    cp16(sb + OFF_BST + (u32)(stg2 * ST1 + i * 16),
                         &g_B1[nt * 1024 + ks2 * 32 + (i & 31)]);
                }
                CP_COMMIT();
            }
            u64 A0 = nA0, A1 = nA1, A2 = nA2, A3 = nA3;
            if (ks < 31) {
                int kp = (ks + 1) * 8 + q;
                nA0 = xr0[kp]; nA1 = xr1[kp]; nA2 = xr0[kp + 4]; nA3 = xr1[kp + 4];
            }
            u32 x1a0 = (u32)A0, x2a0 = (u32)(A0 >> 32);
            u32 x1a1 = (u32)A1, x2a1 = (u32)(A1 >> 32);
            u32 x1a2 = (u32)A2, x2a2 = (u32)(A2 >> 32);
            u32 x1a3 = (u32)A3, x2a3 = (u32)(A3 >> 32);
            const uint4* bp = (const uint4*)(smem + OFF_BST + (ks % 3) * ST1)
                              + wn * 640 + lane;
            #pragma unroll
            for (int j = 0; j < 20; ++j) {
                uint4 B = bp[j * 32];
                hmma(acc[j], x1a0, x1a1, x1a2, x1a3, B.x, B.y);
                hmma(acc[j], x1a0, x1a1, x1a2, x1a3, B.z, B.w);
                hmma(acc[j], x2a0, x2a1, x2a2, x2a3, B.x, B.y);
                hmma(acc[j], x2a0, x2a1, x2a2, x2a3, B.z, B.w);
            }
        }
        __syncthreads();
    }

    // ============ softmax-320 / shrink / bf16-split (from regs) =============
    float* RED0 = (float*)(smem + OFF_RED);          // [2][64] max
    float* RED1 = RED0 + 128;                         // [2][64] expsum
    float* RED2 = RED1 + 128;                         // [2][64] l1
    {
        // round 1: row max
        float m0 = -1e30f, m1 = -1e30f;
        #pragma unroll
        for (int j = 0; j < 20; ++j) {
            m0 = fmaxf(m0, fmaxf(acc[j][0], acc[j][1]));
            m1 = fmaxf(m1, fmaxf(acc[j][2], acc[j][3]));
        }
        m0 = fmaxf(m0, __shfl_xor_sync(0xffffffffu, m0, 1));
        m0 = fmaxf(m0, __shfl_xor_sync(0xffffffffu, m0, 2));
        m1 = fmaxf(m1, __shfl_xor_sync(0xffffffffu, m1, 1));
        m1 = fmaxf(m1, __shfl_xor_sync(0xffffffffu, m1, 2));
        if (q == 0) { RED0[wn * 64 + row] = m0; RED0[wn * 64 + row + 8] = m1; }
        __syncthreads();
        float M0 = fmaxf(RED0[row],     RED0[64 + row]);
        float M1 = fmaxf(RED0[row + 8], RED0[64 + row + 8]);

        // round 2: exp + expsum
        float s0 = 0.0f, s1 = 0.0f;
        #pragma unroll
        for (int j = 0; j < 20; ++j) {
            acc[j][0] = __expf(acc[j][0] - M0);
            acc[j][1] = __expf(acc[j][1] - M0);
            acc[j][2] = __expf(acc[j][2] - M1);
            acc[j][3] = __expf(acc[j][3] - M1);
            s0 += acc[j][0] + acc[j][1];
            s1 += acc[j][2] + acc[j][3];
        }
        s0 += __shfl_xor_sync(0xffffffffu, s0, 1);
        s0 += __shfl_xor_sync(0xffffffffu, s0, 2);
        s1 += __shfl_xor_sync(0xffffffffu, s1, 1);
        s1 += __shfl_xor_sync(0xffffffffu, s1, 2);
        if (q == 0) { RED1[wn * 64 + row] = s0; RED1[wn * 64 + row + 8] = s1; }
        __syncthreads();
        float inv0 = 1.0f / (RED1[row]     + RED1[64 + row]);
        float inv1 = 1.0f / (RED1[row + 8] + RED1[64 + row + 8]);

        // round 3: shrink, l1, store T1/T2 frags
        float l10 = 0.0f, l11 = 0.0f;
        u32* T1 = (u32*)(smem + OFF_T1);
        u32* T2 = (u32*)(smem + OFF_T2);
        #pragma unroll
        for (int j = 0; j < 20; ++j) {
            int col = wn * 160 + j * 8 + 2 * q;
            float a0 = acc[j][0] * inv0, a1 = acc[j][1] * inv0;
            float a2 = acc[j][2] * inv1, a3 = acc[j][3] * inv1;
            float t0 = a0 - SHRINK_L, t1 = a1 - SHRINK_L;
            float t2 = a2 - SHRINK_L, t3 = a3 - SHRINK_L;
            float v0 = fmaxf(t0, 0.0f) * a0 / (fabsf(t0) + EPS_F);
            float v1 = fmaxf(t1, 0.0f) * a1 / (fabsf(t1) + EPS_F);
            float v2 = fmaxf(t2, 0.0f) * a2 / (fabsf(t2) + EPS_F);
            float v3 = fmaxf(t3, 0.0f) * a3 / (fabsf(t3) + EPS_F);
            l10 += v0 + v1; l11 += v2 + v3;
            __nv_bfloat16 b0 = __float2bfloat16(v0), b1 = __float2bfloat16(v1);
            __nv_bfloat16 b2 = __float2bfloat16(v2), b3 = __float2bfloat16(v3);
            float h0 = __bfloat162float(b0), h1 = __bfloat162float(b1);
            float h2 = __bfloat162float(b2), h3 = __bfloat162float(b3);
            int w0 = (row * LSTR + col) >> 1;
            int w1 = ((row + 8) * LSTR + col) >> 1;
            T1[w0] = pack_bf16(h0, h1);
            T1[w1] = pack_bf16(h2, h3);
            T2[w0] = pack_bf16(v0 - h0, v1 - h1);
            T2[w1] = pack_bf16(v2 - h2, v3 - h3);
        }
        l10 += __shfl_xor_sync(0xffffffffu, l10, 1);
        l10 += __shfl_xor_sync(0xffffffffu, l10, 2);
        l11 += __shfl_xor_sync(0xffffffffu, l11, 1);
        l11 += __shfl_xor_sync(0xffffffffu, l11, 2);
        if (q == 0) { RED2[wn * 64 + row] = l10; RED2[wn * 64 + row + 8] = l11; }
        __syncthreads();
    }
    const float sc0 = 1.0f / fmaxf(RED2[row]     + RED2[64 + row],     EPS_F);
    const float sc1 = 1.0f / fmaxf(RED2[row + 8] + RED2[64 + row + 8], EPS_F);

    // ================ GEMM2: out_part [64,512], flattened ===================
    {
        // prologue: fill stages 0,1 (s=0,1)
        #pragma unroll
        for (int s = 0; s < 2; ++s) {
            int hh = 0, ks = s;
            #pragma unroll
            for (int it = 0; it < 4; ++it) {
                int i = tid + it * 256;
                int jj = i >> 5;
                cp16(sb + OFF_BST + (u32)(s * ST2 + i * 16),
                     &g_B2[(hh * 32 + jj) * 640 + ks * 32 + (i & 31)]);
            }
            CP_COMMIT();
        }

        float acc2[16][4];
        for (int s = 0; s < 40; ++s) {
            int hh = s / 20, ks = s % 20;
            if (ks == 0) {
                #pragma unroll
                for (int j = 0; j < 16; ++j)
                    #pragma unroll
                    for (int e = 0; e < 4; ++e) acc2[j][e] = 0.0f;
            }
            if (s >= 38) { CP_WAIT0(); } else { CP_WAIT1(); }
            __syncthreads();
            if (s + 2 < 40) {
                int s2 = s + 2;
                int hh2 = s2 / 20, ks2 = s2 % 20, stg2 = s2 % 3;
                #pragma unroll
                for (int it = 0; it < 4; ++it) {
                    int i = tid + it * 256;
                    int jj = i >> 5;
                    cp16(sb + OFF_BST + (u32)(stg2 * ST2 + i * 16),
                         &g_B2[(hh2 * 32 + jj) * 640 + ks2 * 32 + (i & 31)]);
                }
                CP_COMMIT();
            }
            int kb = ks * 16 + 2 * q;
            const u32* T1 = (const u32*)(smem + OFF_T1);
            const u32* T2 = (const u32*)(smem + OFF_T2);
            u32 a10 = T1[(row * LSTR + kb) >> 1];
            u32 a11 = T1[((row + 8) * LSTR + kb) >> 1];
            u32 a12 = T1[(row * LSTR + kb + 8) >> 1];
            u32 a13 = T1[((row + 8) * LSTR + kb + 8) >> 1];
            u32 a20 = T2[(row * LSTR + kb) >> 1];
            u32 a21 = T2[((row + 8) * LSTR + kb) >> 1];
            u32 a22 = T2[(row * LSTR + kb + 8) >> 1];
            u32 a23 = T2[((row + 8) * LSTR + kb + 8) >> 1];
            const uint4* bp = (const uint4*)(smem + OFF_BST + (s % 3) * ST2)
                              + wn * 512 + lane;
            #pragma unroll
            for (int j = 0; j < 16; ++j) {
                uint4 B = bp[j * 32];
                hmma(acc2[j], a10, a11, a12, a13, B.x, B.y);
                hmma(acc2[j], a10, a11, a12, a13, B.z, B.w);
                hmma(acc2[j], a20, a21, a22, a23, B.x, B.y);
            }

            if (ks == 19) {
                size_t gr = (size_t)(rowbase + row);
                #pragma unroll
                for (int j = 0; j < 16; ++j) {
                    int col = hh * 256 + wn * 128 + j * 8 + 2 * q;
                    float2 p0; p0.x = acc2[j][0] * sc0; p0.y = acc2[j][1] * sc0;
                    float2 p1; p1.x = acc2[j][2] * sc1; p1.y = acc2[j][3] * sc1;
                    *(float2*)(out_part + gr * CDIM + col)       = p0;
                    *(float2*)(out_part + (gr + 8) * CDIM + col) = p1;
                }
            }
        }
    }
}

// ---------------------------------------------------------------------------
extern "C" void kernel_launch(void* const* d_in, const int* in_sizes, int n_in,
                              void* d_out, int out_size) {
    const float* X  = (const float*)d_in[0];
    const float* W  = (const float*)d_in[1];
    const float* wp = (const float*)d_in[2];
    const float* bp = (const float*)d_in[3];
    const float* wi = (const float*)d_in[4];
    const float* bi = (const float*)d_in[5];

    int N = in_sizes[0] / CDIM;   // 131072

    float* out      = (float*)d_out;
    float* out_sem  = out;                                   // [N, 512]
    float* out_att  = out + (size_t)N * CDIM;                // [N, 10]
    float* out_semm = out_att + (size_t)N * LCLS;            // [10, 512]
    float* out_part = out_semm + (size_t)LCLS * CDIM;        // [N, 512]

    sem_build_kernel<<<1, 512>>>(W, wp, bp, wi, bi, out_semm);
    int n4 = N * CDIM / 4;
    xsplit_kernel<<<(n4 + 255) / 256, 256>>>(X, n4);
    bfrag1_kernel<<<(40 * 32 * 32 + 255) / 256, 256>>>(W);
    bfrag2_kernel<<<(64 * 20 * 32 + 255) / 256, 256>>>(W);

    cudaFuncSetAttribute(fused_kernel,
                         cudaFuncAttributeMaxDynamicSharedMemorySize, SMEM_BYTES);
    fused_kernel<<<N / BM, THREADS, SMEM_BYTES>>>(X, out_sem, out_att, out_part);
}

// round 15
// speedup vs baseline: 2.9177x; 1.1603x over previous
#include <cuda_runtime.h>
#include <cuda_bf16.h>

typedef unsigned int u32;
typedef unsigned long long u64;

#define CDIM 512
#define MDIM 320
#define LCLS 10
#define SHRINK_L 0.0025f
#define EPS_F 1e-12f
#define BM 64
#define THREADS 256
#define NMAX 131072
#define LSTR 322

// ---- shared memory byte offsets (aggressive phase overlap for occupancy 2) ----
// T1 [0, 41216)             -- written in epilogue, read in GEMM2
// T2 [41216, 82432)         -- written in epilogue, read in GEMM2
// SEM [0, 20480)            -- phase A only (dead before GEMM1)
// G1 ring [0, 61440)        -- GEMM1 only (dead before epilogue writes T)
// RED [82432, 83968)        -- epilogue only (read out before GEMM2 fills)
// G2 ring [82432, 115200)   -- GEMM2 only (2 stages x 16384)
#define OFF_SEM  0
#define OFF_T1   0
#define OFF_T2   41216
#define OFF_G1   0
#define ST1      20480
#define OFF_RED  82432
#define OFF_G2   82432
#define ST2      16384
#define SMEM_BYTES 115200

// ---- global scratch ----
__device__ u64  g_Xi[(size_t)NMAX * 256];   // {x1 pair, x2 pair} per 2 cols
__device__ uint4 g_B1[40 * 32 * 32];        // GEMM1 B frags [nt][ks][lane]
__device__ uint4 g_B2[64 * 20 * 32];        // GEMM2 B frags [nt][ks][lane]
__device__ float g_sem[LCLS * CDIM];

__device__ __forceinline__ float sigmoidf_(float x) { return 1.0f / (1.0f + __expf(-x)); }

__device__ __forceinline__ u32 pack_bf16(float lo, float hi) {
    __nv_bfloat162 h2 = __floats2bfloat162_rn(lo, hi);
    return *reinterpret_cast<u32*>(&h2);
}

__device__ __forceinline__ u32 smem_u32(const void* p) {
    u32 a;
    asm("{ .reg .u64 t; cvta.to.shared.u64 t, %1; cvt.u32.u64 %0, t; }" : "=r"(a) : "l"(p));
    return a;
}

__device__ __forceinline__ void cp16(u32 dst, const void* src) {
    asm volatile("cp.async.cg.shared.global [%0], [%1], 16;" :: "r"(dst), "l"(src) : "memory");
}
#define CP_COMMIT() asm volatile("cp.async.commit_group;" ::: "memory")
#define CP_WAIT0()  asm volatile("cp.async.wait_group 0;" ::: "memory")
#define CP_WAIT1()  asm volatile("cp.async.wait_group 1;" ::: "memory")

__device__ __forceinline__ void hmma(float* c, u32 a0, u32 a1, u32 a2, u32 a3,
                                     u32 b0, u32 b1) {
    asm volatile(
        "mma.sync.aligned.m16n8k16.row.col.f32.bf16.bf16.f32 "
        "{%0,%1,%2,%3}, {%4,%5,%6,%7}, {%8,%9}, {%0,%1,%2,%3};"
        : "+f"(c[0]), "+f"(c[1]), "+f"(c[2]), "+f"(c[3])
        : "r"(a0), "r"(a1), "r"(a2), "r"(a3), "r"(b0), "r"(b1));
}

// ---------------------------------------------------------------------------
// Prologue 1: sem_att build
// ---------------------------------------------------------------------------
__global__ void sem_build_kernel(const float* __restrict__ W,
                                 const float* __restrict__ wp,
                                 const float* __restrict__ bp,
                                 const float* __restrict__ wi,
                                 const float* __restrict__ bi,
                                 float* __restrict__ out_semmat) {
    int c = threadIdx.x;
    if (c >= CDIM) return;
    float wpl[16], bpl[4], wil[64], bil[8];
    #pragma unroll
    for (int i = 0; i < 16; ++i) wpl[i] = wp[i];
    #pragma unroll
    for (int i = 0; i < 4; ++i) bpl[i] = bp[i];
    #pragma unroll
    for (int i = 0; i < 64; ++i) wil[i] = wi[i];
    #pragma unroll
    for (int i = 0; i < 8; ++i) bil[i] = bi[i];

    for (int l = 0; l < LCLS; ++l) {
        float pt[8];
        #pragma unroll
        for (int t = 0; t < 8; ++t) {
            int n = l * 8 + t;
            float4 r4 = *(const float4*)(W + n * 2048 + c * 4);
            float rp[4] = {r4.x, r4.y, r4.z, r4.w};
            float acc = 0.0f;
            #pragma unroll
            for (int q = 0; q < 4; ++q) {
                float s = bpl[q];
                #pragma unroll
                for (int p = 0; p < 4; ++p) s += wpl[q * 4 + p] * rp[p];
                acc += sigmoidf_(s) * rp[q];
            }
            pt[t] = acc * 0.25f;
        }
        float acc2 = 0.0f;
        #pragma unroll
        for (int q = 0; q < 8; ++q) {
            float s = bil[q];
            #pragma unroll
            for (int t = 0; t < 8; ++t) s += wil[q * 8 + t] * pt[t];
            acc2 += sigmoidf_(s) * pt[q];
        }
        float v = acc2 * 0.125f;
        g_sem[l * CDIM + c] = v;
        out_semmat[l * CDIM + c] = v;
    }
}

// ---------------------------------------------------------------------------
// Prologue 2: split X into interleaved bf16 pairs
// ---------------------------------------------------------------------------
__global__ void xsplit_kernel(const float* __restrict__ X, int n4) {
    int i = blockIdx.x * 256 + threadIdx.x;
    if (i >= n4) return;
    float4 v = *(const float4*)(X + (size_t)i * 4);
    float vf[4] = {v.x, v.y, v.z, v.w};
    float h[4], l[4];
    #pragma unroll
    for (int e = 0; e < 4; ++e) {
        __nv_bfloat16 b = __float2bfloat16(vf[e]);
        h[e] = __bfloat162float(b);
        l[e] = vf[e] - h[e];
    }
    uint4 o;
    o.x = pack_bf16(h[0], h[1]);
    o.y = pack_bf16(l[0], l[1]);
    o.z = pack_bf16(h[2], h[3]);
    o.w = pack_bf16(l[2], l[3]);
    ((uint4*)g_Xi)[i] = o;
}

// ---------------------------------------------------------------------------
// Prologue 3: W fragments for GEMM1 (B = W^T)
// ---------------------------------------------------------------------------
__global__ void bfrag1_kernel(const float* __restrict__ W) {
    int idx = blockIdx.x * 256 + threadIdx.x;
    if (idx >= 40 * 32 * 32) return;
    int nt = idx >> 10, ks = (idx >> 5) & 31, l = idx & 31;
    int n = nt * 8 + (l >> 2);
    int kb = ks * 16 + 2 * (l & 3);
    float v[4] = { W[n * CDIM + kb], W[n * CDIM + kb + 1],
                   W[n * CDIM + kb + 8], W[n * CDIM + kb + 9] };
    float h[4], r[4];
    #pragma unroll
    for (int e = 0; e < 4; ++e) {
        __nv_bfloat16 b = __float2bfloat16(v[e]);
        h[e] = __bfloat162float(b);
        r[e] = v[e] - h[e];
    }
    uint4 o;
    o.x = pack_bf16(h[0], h[1]);
    o.y = pack_bf16(h[2], h[3]);
    o.z = pack_bf16(r[0], r[1]);
    o.w = pack_bf16(r[2], r[3]);
    g_B1[idx] = o;
}

// ---------------------------------------------------------------------------
// Prologue 4: W fragments for GEMM2 (B = W)
// ---------------------------------------------------------------------------
__global__ void bfrag2_kernel(const float* __restrict__ W) {
    int idx = blockIdx.x * 256 + threadIdx.x;
    if (idx >= 64 * 20 * 32) return;
    int nt = idx / 640, rem = idx % 640;
    int ks = rem >> 5, l = rem & 31;
    int n = nt * 8 + (l >> 2);
    int kb = ks * 16 + 2 * (l & 3);
    float v[4] = { W[kb * CDIM + n], W[(kb + 1) * CDIM + n],
                   W[(kb + 8) * CDIM + n], W[(kb + 9) * CDIM + n] };
    float h[4], r[4];
    #pragma unroll
    for (int e = 0; e < 4; ++e) {
        __nv_bfloat16 b = __float2bfloat16(v[e]);
        h[e] = __bfloat162float(b);
        r[e] = v[e] - h[e];
    }
    uint4 o;
    o.x = pack_bf16(h[0], h[1]);
    o.y = pack_bf16(h[2], h[3]);
    o.z = pack_bf16(r[0], r[1]);
    o.w = pack_bf16(r[2], r[3]);
    g_B2[idx] = o;
}

// ---------------------------------------------------------------------------
// Main fused kernel (2 CTAs / SM)
// ---------------------------------------------------------------------------
__global__ __launch_bounds__(THREADS, 2)
void fused_kernel(const float* __restrict__ X,
                  float* __restrict__ out_sem,
                  float* __restrict__ out_att,
                  float* __restrict__ out_part) {
    extern __shared__ char smem[];
    const u32 sb = smem_u32(smem);
    const int tid = threadIdx.x;
    const int wid = tid >> 5;
    const int lane = tid & 31;
    const int rowbase = blockIdx.x * BM;

    // =========================== Phase A: stage-3 ===========================
    {
        float* SEM = (float*)(smem + OFF_SEM);
        for (int i = tid; i < LCLS * CDIM / 4; i += THREADS)
            ((float4*)SEM)[i] = ((const float4*)g_sem)[i];
        __syncthreads();

        const int r = tid >> 2, h = tid & 3;
        const float4* xp = (const float4*)(X + (size_t)(rowbase + r) * CDIM);
        float s3[LCLS];
        #pragma unroll
        for (int l = 0; l < LCLS; ++l) s3[l] = 0.0f;

        #pragma unroll 4
        for (int u = 0; u < 32; ++u) {
            float4 xv = xp[u * 4 + h];
            int cc = u * 16 + h * 4;
            #pragma unroll
            for (int l = 0; l < LCLS; ++l) {
                float4 sv = *(const float4*)&SEM[l * CDIM + cc];
                s3[l] += xv.x * sv.x + xv.y * sv.y + xv.z * sv.z + xv.w * sv.w;
            }
        }
        #pragma unroll
        for (int l = 0; l < LCLS; ++l) {
            s3[l] += __shfl_xor_sync(0xffffffffu, s3[l], 1);
            s3[l] += __shfl_xor_sync(0xffffffffu, s3[l], 2);
        }

        float mx = s3[0];
        #pragma unroll
        for (int l = 1; l < LCLS; ++l) mx = fmaxf(mx, s3[l]);
        float se = 0.0f;
        #pragma unroll
        for (int l = 0; l < LCLS; ++l) { s3[l] = __expf(s3[l] - mx); se += s3[l]; }
        float inv = 1.0f / se;
        float l1 = 0.0f;
        #pragma unroll
        for (int l = 0; l < LCLS; ++l) {
            float a = s3[l] * inv;
            float t = a - SHRINK_L;
            float v = fmaxf(t, 0.0f) * a / (fabsf(t) + EPS_F);
            s3[l] = v; l1 += v;
        }
        float sc = 1.0f / fmaxf(l1, EPS_F);
        #pragma unroll
        for (int l = 0; l < LCLS; ++l) s3[l] *= sc;
        if (h == 0) {
            #pragma unroll
            for (int l = 0; l < LCLS; ++l)
                out_att[(size_t)(rowbase + r) * LCLS + l] = s3[l];
        }
        float4* op = (float4*)(out_sem + (size_t)(rowbase + r) * CDIM);
        #pragma unroll 4
        for (int u = 0; u < 32; ++u) {
            int cc = u * 16 + h * 4;
            float4 acc = make_float4(0.f, 0.f, 0.f, 0.f);
            #pragma unroll
            for (int l = 0; l < LCLS; ++l) {
                float4 sv = *(const float4*)&SEM[l * CDIM + cc];
                acc.x += s3[l] * sv.x; acc.y += s3[l] * sv.y;
                acc.z += s3[l] * sv.z; acc.w += s3[l] * sv.w;
            }
            op[u * 4 + h] = acc;
        }
        __syncthreads();
    }

    const int wm = wid >> 1;          // 0..3 (M tile)
    const int wn = wid & 1;           // 0..1 (N half)
    const int qr = lane >> 2;         // 0..7
    const int q  = lane & 3;          // 0..3
    const int row = wm * 16 + qr;

    // ====================== GEMM1: logits [64,320] ==========================
    float acc[20][4];
    {
        #pragma unroll
        for (int j = 0; j < 20; ++j)
            #pragma unroll
            for (int e = 0; e < 4; ++e) acc[j][e] = 0.0f;

        const u64* xr0 = g_Xi + (size_t)(rowbase + row) * 256;
        const u64* xr1 = xr0 + 8 * 256;

        // prologue: fill stages 0,1 (ks=0,1)
        #pragma unroll
        for (int s = 0; s < 2; ++s) {
            #pragma unroll
            for (int it = 0; it < 5; ++it) {
                int i = tid + it * 256;
                int nt = i >> 5;
                cp16(sb + OFF_G1 + (u32)(s * ST1 + i * 16),
                     &g_B1[nt * 1024 + s * 32 + (i & 31)]);
            }
            CP_COMMIT();
        }
        // prefetch A for ks=0
        u64 nA0 = xr0[q], nA1 = xr1[q], nA2 = xr0[q + 4], nA3 = xr1[q + 4];

        for (int ks = 0; ks < 32; ++ks) {
            if (ks >= 30) { CP_WAIT0(); } else { CP_WAIT1(); }
            __syncthreads();
            if (ks + 2 < 32) {
                int ks2 = ks + 2, stg2 = ks2 % 3;
                #pragma unroll
                for (int it = 0; it < 5; ++it) {
                    int i = tid + it * 256;
                    int nt = i >> 5;
                    cp16(sb + OFF_G1 + (u32)(stg2 * ST1 + i * 16),
                         &g_B1[nt * 1024 + ks2 * 32 + (i & 31)]);
                }
                CP_COMMIT();
            }
            u64 A0 = nA0, A1 = nA1, A2 = nA2, A3 = nA3;
            if (ks < 31) {
                int kp = (ks + 1) * 8 + q;
                nA0 = xr0[kp]; nA1 = xr1[kp]; nA2 = xr0[kp + 4]; nA3 = xr1[kp + 4];
            }
            u32 x1a0 = (u32)A0, x2a0 = (u32)(A0 >> 32);
            u32 x1a1 = (u32)A1, x2a1 = (u32)(A1 >> 32);
            u32 x1a2 = (u32)A2, x2a2 = (u32)(A2 >> 32);
            u32 x1a3 = (u32)A3, x2a3 = (u32)(A3 >> 32);
            const uint4* bp = (const uint4*)(smem + OFF_G1 + (ks % 3) * ST1)
                              + wn * 640 + lane;
            #pragma unroll
            for (int j = 0; j < 20; ++j) {
                uint4 B = bp[j * 32];
                hmma(acc[j], x1a0, x1a1, x1a2, x1a3, B.x, B.y);
                hmma(acc[j], x1a0, x1a1, x1a2, x1a3, B.z, B.w);
                hmma(acc[j], x2a0, x2a1, x2a2, x2a3, B.x, B.y);
                hmma(acc[j], x2a0, x2a1, x2a2, x2a3, B.z, B.w);
            }
        }
        __syncthreads();
    }

    // ============ softmax-320 / shrink / bf16-split (from regs) =============
    float* RED0 = (float*)(smem + OFF_RED);          // [2][64] max
    float* RED1 = RED0 + 128;                         // [2][64] expsum
    float* RED2 = RED1 + 128;                         // [2][64] l1
    {
        // round 1: row max
        float m0 = -1e30f, m1 = -1e30f;
        #pragma unroll
        for (int j = 0; j < 20; ++j) {
            m0 = fmaxf(m0, fmaxf(acc[j][0], acc[j][1]));
            m1 = fmaxf(m1, fmaxf(acc[j][2], acc[j][3]));
        }
        m0 = fmaxf(m0, __shfl_xor_sync(0xffffffffu, m0, 1));
        m0 = fmaxf(m0, __shfl_xor_sync(0xffffffffu, m0, 2));
        m1 = fmaxf(m1, __shfl_xor_sync(0xffffffffu, m1, 1));
        m1 = fmaxf(m1, __shfl_xor_sync(0xffffffffu, m1, 2));
        if (q == 0) { RED0[wn * 64 + row] = m0; RED0[wn * 64 + row + 8] = m1; }
        __syncthreads();
        float M0 = fmaxf(RED0[row],     RED0[64 + row]);
        float M1 = fmaxf(RED0[row + 8], RED0[64 + row + 8]);

        // round 2: exp + expsum
        float s0 = 0.0f, s1 = 0.0f;
        #pragma unroll
        for (int j = 0; j < 20; ++j) {
            acc[j][0] = __expf(acc[j][0] - M0);
            acc[j][1] = __expf(acc[j][1] - M0);
            acc[j][2] = __expf(acc[j][2] - M1);
            acc[j][3] = __expf(acc[j][3] - M1);
            s0 += acc[j][0] + acc[j][1];
            s1 += acc[j][2] + acc[j][3];
        }
        s0 += __shfl_xor_sync(0xffffffffu, s0, 1);
        s0 += __shfl_xor_sync(0xffffffffu, s0, 2);
        s1 += __shfl_xor_sync(0xffffffffu, s1, 1);
        s1 += __shfl_xor_sync(0xffffffffu, s1, 2);
        if (q == 0) { RED1[wn * 64 + row] = s0; RED1[wn * 64 + row + 8] = s1; }
        __syncthreads();
        float inv0 = 1.0f / (RED1[row]     + RED1[64 + row]);
        float inv1 = 1.0f / (RED1[row + 8] + RED1[64 + row + 8]);

        // round 3: shrink, l1, store T1/T2 frags
        float l10 = 0.0f, l11 = 0.0f;
        u32* T1 = (u32*)(smem + OFF_T1);
        u32* T2 = (u32*)(smem + OFF_T2);
        #pragma unroll
        for (int j = 0; j < 20; ++j) {
            int col = wn * 160 + j * 8 + 2 * q;
            float a0 = acc[j][0] * inv0, a1 = acc[j][1] * inv0;
            float a2 = acc[j][2] * inv1, a3 = acc[j][3] * inv1;
            float t0 = a0 - SHRINK_L, t1 = a1 - SHRINK_L;
            float t2 = a2 - SHRINK_L, t3 = a3 - SHRINK_L;
            float v0 = fmaxf(t0, 0.0f) * a0 / (fabsf(t0) + EPS_F);
            float v1 = fmaxf(t1, 0.0f) * a1 / (fabsf(t1) + EPS_F);
            float v2 = fmaxf(t2, 0.0f) * a2 / (fabsf(t2) + EPS_F);
            float v3 = fmaxf(t3, 0.0f) * a3 / (fabsf(t3) + EPS_F);
            l10 += v0 + v1; l11 += v2 + v3;
            __nv_bfloat16 b0 = __float2bfloat16(v0), b1 = __float2bfloat16(v1);
            __nv_bfloat16 b2 = __float2bfloat16(v2), b3 = __float2bfloat16(v3);
            float h0 = __bfloat162float(b0), h1 = __bfloat162float(b1);
            float h2 = __bfloat162float(b2), h3 = __bfloat162float(b3);
            int w0 = (row * LSTR + col) >> 1;
            int w1 = ((row + 8) * LSTR + col) >> 1;
            T1[w0] = pack_bf16(h0, h1);
            T1[w1] = pack_bf16(h2, h3);
            T2[w0] = pack_bf16(v0 - h0, v1 - h1);
            T2[w1] = pack_bf16(v2 - h2, v3 - h3);
        }
        l10 += __shfl_xor_sync(0xffffffffu, l10, 1);
        l10 += __shfl_xor_sync(0xffffffffu, l10, 2);
        l11 += __shfl_xor_sync(0xffffffffu, l11, 1);
        l11 += __shfl_xor_sync(0xffffffffu, l11, 2);
        if (q == 0) { RED2[wn * 64 + row] = l10; RED2[wn * 64 + row + 8] = l11; }
        __syncthreads();
    }
    const float sc0 = 1.0f / fmaxf(RED2[row]     + RED2[64 + row],     EPS_F);
    const float sc1 = 1.0f / fmaxf(RED2[row + 8] + RED2[64 + row + 8], EPS_F);
    __syncthreads();   // all RED reads done before the G2 ring reuses that space

    // ================ GEMM2: out_part [64,512], flattened ===================
    {
        // prologue: fill stages 0,1 (s=0,1 -> hh=0, ks=0,1)
        #pragma unroll
        for (int s = 0; s < 2; ++s) {
            #pragma unroll
            for (int it = 0; it < 4; ++it) {
                int i = tid + it * 256;
                int jj = i >> 5;
                cp16(sb + OFF_G2 + (u32)(s * ST2 + i * 16),
                     &g_B2[jj * 640 + s * 32 + (i & 31)]);
            }
            CP_COMMIT();
        }

        float acc2[16][4];
        for (int s = 0; s < 40; ++s) {
            int hh = s / 20, ks = s % 20;
            if (ks == 0) {
                #pragma unroll
                for (int j = 0; j < 16; ++j)
                    #pragma unroll
                    for (int e = 0; e < 4; ++e) acc2[j][e] = 0.0f;
            }
            if (s >= 38) { CP_WAIT0(); } else { CP_WAIT1(); }
            __syncthreads();

            int kb = ks * 16 + 2 * q;
            const u32* T1 = (const u32*)(smem + OFF_T1);
            const u32* T2 = (const u32*)(smem + OFF_T2);
            u32 a10 = T1[(row * LSTR + kb) >> 1];
            u32 a11 = T1[((row + 8) * LSTR + kb) >> 1];
            u32 a12 = T1[(row * LSTR + kb + 8) >> 1];
            u32 a13 = T1[((row + 8) * LSTR + kb + 8) >> 1];
            u32 a20 = T2[(row * LSTR + kb) >> 1];
            u32 a21 = T2[((row + 8) * LSTR + kb) >> 1];
            u32 a22 = T2[(row * LSTR + kb + 8) >> 1];
            u32 a23 = T2[((row + 8) * LSTR + kb + 8) >> 1];
            const uint4* bp = (const uint4*)(smem + OFF_G2 + (s & 1) * ST2)
                              + wn * 512 + lane;
            #pragma unroll
            for (int j = 0; j < 16; ++j) {
                uint4 B = bp[j * 32];
                hmma(acc2[j], a10, a11, a12, a13, B.x, B.y);
                hmma(acc2[j], a10, a11, a12, a13, B.z, B.w);
                hmma(acc2[j], a20, a21, a22, a23, B.x, B.y);
            }

            if (ks == 19) {
                size_t gr = (size_t)(rowbase + row);
                #pragma unroll
                for (int j = 0; j < 16; ++j) {
                    int col = hh * 256 + wn * 128 + j * 8 + 2 * q;
                    float2 p0; p0.x = acc2[j][0] * sc0; p0.y = acc2[j][1] * sc0;
                    float2 p1; p1.x = acc2[j][2] * sc1; p1.y = acc2[j][3] * sc1;
                    *(float2*)(out_part + gr * CDIM + col)       = p0;
                    *(float2*)(out_part + (gr + 8) * CDIM + col) = p1;
                }
            }

            if (s + 2 < 40) {
                __syncthreads();   // everyone done reading stage s&1 before refill
                int s2 = s + 2;
                int hh2 = s2 / 20, ks2 = s2 % 20;
                #pragma unroll
                for (int it = 0; it < 4; ++it) {
                    int i = tid + it * 256;
                    int jj = i >> 5;
                    cp16(sb + OFF_G2 + (u32)((s & 1) * ST2 + i * 16),
                         &g_B2[(hh2 * 32 + jj) * 640 + ks2 * 32 + (i & 31)]);
                }
                CP_COMMIT();
            }
        }
    }
}

// ---------------------------------------------------------------------------
extern "C" void kernel_launch(void* const* d_in, const int* in_sizes, int n_in,
                              void* d_out, int out_size) {
    const float* X  = (const float*)d_in[0];
    const float* W  = (const float*)d_in[1];
    const float* wp = (const float*)d_in[2];
    const float* bp = (const float*)d_in[3];
    const float* wi = (const float*)d_in[4];
    const float* bi = (const float*)d_in[5];

    int N = in_sizes[0] / CDIM;   // 131072

    float* out      = (float*)d_out;
    float* out_sem  = out;                                   // [N, 512]
    float* out_att  = out + (size_t)N * CDIM;                // [N, 10]
    float* out_semm = out_att + (size_t)N * LCLS;            // [10, 512]
    float* out_part = out_semm + (size_t)LCLS * CDIM;        // [N, 512]

    sem_build_kernel<<<1, 512>>>(W, wp, bp, wi, bi, out_semm);
    int n4 = N * CDIM / 4;
    xsplit_kernel<<<(n4 + 255) / 256, 256>>>(X, n4);
    bfrag1_kernel<<<(40 * 32 * 32 + 255) / 256, 256>>>(W);
    bfrag2_kernel<<<(64 * 20 * 32 + 255) / 256, 256>>>(W);

    cudaFuncSetAttribute(fused_kernel,
                         cudaFuncAttributeMaxDynamicSharedMemorySize, SMEM_BYTES);
    fused_kernel<<<N / BM, THREADS, SMEM_BYTES>>>(X, out_sem, out_att, out_part);
}

// round 16
// speedup vs baseline: 3.4519x; 1.1831x over previous
#include <cuda_runtime.h>
#include <cuda_bf16.h>

typedef unsigned int u32;
typedef unsigned long long u64;

#define CDIM 512
#define MDIM 320
#define LCLS 10
#define SHRINK_L 0.0025f
#define EPS_F 1e-12f
#define BM 64
#define THREADS 256
#define NMAX 131072
#define LSTR 322

// ---- shared memory byte offsets (aggressive phase overlap for occupancy 2) ----
#define OFF_SEM  0
#define OFF_T1   0
#define OFF_T2   41216
#define OFF_G1   0
#define ST1      20480
#define OFF_RED  82432
#define OFF_G2   82432
#define ST2      16384
#define SMEM_BYTES 115200

// ---- global scratch ----
__device__ u64  g_Xi[(size_t)NMAX * 256];   // {x1 pair, x2 pair} per 2 cols (written in-kernel)
__device__ uint4 g_B1[40 * 32 * 32];        // GEMM1 B frags [nt][ks][lane]
__device__ uint4 g_B2[64 * 20 * 32];        // GEMM2 B frags [nt][ks][lane]
__device__ float g_sem[LCLS * CDIM];

__device__ __forceinline__ float sigmoidf_(float x) { return 1.0f / (1.0f + __expf(-x)); }

__device__ __forceinline__ u32 pack_bf16(float lo, float hi) {
    __nv_bfloat162 h2 = __floats2bfloat162_rn(lo, hi);
    return *reinterpret_cast<u32*>(&h2);
}

__device__ __forceinline__ u32 smem_u32(const void* p) {
    u32 a;
    asm("{ .reg .u64 t; cvta.to.shared.u64 t, %1; cvt.u32.u64 %0, t; }" : "=r"(a) : "l"(p));
    return a;
}

__device__ __forceinline__ void cp16(u32 dst, const void* src) {
    asm volatile("cp.async.cg.shared.global [%0], [%1], 16;" :: "r"(dst), "l"(src) : "memory");
}
#define CP_COMMIT() asm volatile("cp.async.commit_group;" ::: "memory")
#define CP_WAIT0()  asm volatile("cp.async.wait_group 0;" ::: "memory")
#define CP_WAIT1()  asm volatile("cp.async.wait_group 1;" ::: "memory")

__device__ __forceinline__ void hmma(float* c, u32 a0, u32 a1, u32 a2, u32 a3,
                                     u32 b0, u32 b1) {
    asm volatile(
        "mma.sync.aligned.m16n8k16.row.col.f32.bf16.bf16.f32 "
        "{%0,%1,%2,%3}, {%4,%5,%6,%7}, {%8,%9}, {%0,%1,%2,%3};"
        : "+f"(c[0]), "+f"(c[1]), "+f"(c[2]), "+f"(c[3])
        : "r"(a0), "r"(a1), "r"(a2), "r"(a3), "r"(b0), "r"(b1));
}

// ---------------------------------------------------------------------------
// Prologue 1: sem_att build
// ---------------------------------------------------------------------------
__global__ void sem_build_kernel(const float* __restrict__ W,
                                 const float* __restrict__ wp,
                                 const float* __restrict__ bp,
                                 const float* __restrict__ wi,
                                 const float* __restrict__ bi,
                                 float* __restrict__ out_semmat) {
    int c = threadIdx.x;
    if (c >= CDIM) return;
    float wpl[16], bpl[4], wil[64], bil[8];
    #pragma unroll
    for (int i = 0; i < 16; ++i) wpl[i] = wp[i];
    #pragma unroll
    for (int i = 0; i < 4; ++i) bpl[i] = bp[i];
    #pragma unroll
    for (int i = 0; i < 64; ++i) wil[i] = wi[i];
    #pragma unroll
    for (int i = 0; i < 8; ++i) bil[i] = bi[i];

    for (int l = 0; l < LCLS; ++l) {
        float pt[8];
        #pragma unroll
        for (int t = 0; t < 8; ++t) {
            int n = l * 8 + t;
            float4 r4 = *(const float4*)(W + n * 2048 + c * 4);
            float rp[4] = {r4.x, r4.y, r4.z, r4.w};
            float acc = 0.0f;
            #pragma unroll
            for (int q = 0; q < 4; ++q) {
                float s = bpl[q];
                #pragma unroll
                for (int p = 0; p < 4; ++p) s += wpl[q * 4 + p] * rp[p];
                acc += sigmoidf_(s) * rp[q];
            }
            pt[t] = acc * 0.25f;
        }
        float acc2 = 0.0f;
        #pragma unroll
        for (int q = 0; q < 8; ++q) {
            float s = bil[q];
            #pragma unroll
            for (int t = 0; t < 8; ++t) s += wil[q * 8 + t] * pt[t];
            acc2 += sigmoidf_(s) * pt[q];
        }
        float v = acc2 * 0.125f;
        g_sem[l * CDIM + c] = v;
        out_semmat[l * CDIM + c] = v;
    }
}

// ---------------------------------------------------------------------------
// Prologue 2: W fragments for GEMM1 (B = W^T)
// ---------------------------------------------------------------------------
__global__ void bfrag1_kernel(const float* __restrict__ W) {
    int idx = blockIdx.x * 256 + threadIdx.x;
    if (idx >= 40 * 32 * 32) return;
    int nt = idx >> 10, ks = (idx >> 5) & 31, l = idx & 31;
    int n = nt * 8 + (l >> 2);
    int kb = ks * 16 + 2 * (l & 3);
    float v[4] = { W[n * CDIM + kb], W[n * CDIM + kb + 1],
                   W[n * CDIM + kb + 8], W[n * CDIM + kb + 9] };
    float h[4], r[4];
    #pragma unroll
    for (int e = 0; e < 4; ++e) {
        __nv_bfloat16 b = __float2bfloat16(v[e]);
        h[e] = __bfloat162float(b);
        r[e] = v[e] - h[e];
    }
    uint4 o;
    o.x = pack_bf16(h[0], h[1]);
    o.y = pack_bf16(h[2], h[3]);
    o.z = pack_bf16(r[0], r[1]);
    o.w = pack_bf16(r[2], r[3]);
    g_B1[idx] = o;
}

// ---------------------------------------------------------------------------
// Prologue 3: W fragments for GEMM2 (B = W)
// ---------------------------------------------------------------------------
__global__ void bfrag2_kernel(const float* __restrict__ W) {
    int idx = blockIdx.x * 256 + threadIdx.x;
    if (idx >= 64 * 20 * 32) return;
    int nt = idx / 640, rem = idx % 640;
    int ks = rem >> 5, l = rem & 31;
    int n = nt * 8 + (l >> 2);
    int kb = ks * 16 + 2 * (l & 3);
    float v[4] = { W[kb * CDIM + n], W[(kb + 1) * CDIM + n],
                   W[(kb + 8) * CDIM + n], W[(kb + 9) * CDIM + n] };
    float h[4], r[4];
    #pragma unroll
    for (int e = 0; e < 4; ++e) {
        __nv_bfloat16 b = __float2bfloat16(v[e]);
        h[e] = __bfloat162float(b);
        r[e] = v[e] - h[e];
    }
    uint4 o;
    o.x = pack_bf16(h[0], h[1]);
    o.y = pack_bf16(h[2], h[3]);
    o.z = pack_bf16(r[0], r[1]);
    o.w = pack_bf16(r[2], r[3]);
    g_B2[idx] = o;
}

// ---------------------------------------------------------------------------
// Main fused kernel (2 CTAs / SM)
// ---------------------------------------------------------------------------
__global__ __launch_bounds__(THREADS, 2)
void fused_kernel(const float* __restrict__ X,
                  float* __restrict__ out_sem,
                  float* __restrict__ out_att,
                  float* __restrict__ out_part) {
    extern __shared__ char smem[];
    const u32 sb = smem_u32(smem);
    const int tid = threadIdx.x;
    const int wid = tid >> 5;
    const int lane = tid & 31;
    const int rowbase = blockIdx.x * BM;

    // ============ Phase A: stage-3 attend + produce g_Xi splits =============
    {
        float* SEM = (float*)(smem + OFF_SEM);
        for (int i = tid; i < LCLS * CDIM / 4; i += THREADS)
            ((float4*)SEM)[i] = ((const float4*)g_sem)[i];
        __syncthreads();

        const int r = tid >> 2, h = tid & 3;
        const float4* xp = (const float4*)(X + (size_t)(rowbase + r) * CDIM);
        uint4* xi = ((uint4*)g_Xi) + (size_t)(rowbase + r) * 128;
        float s3[LCLS];
        #pragma unroll
        for (int l = 0; l < LCLS; ++l) s3[l] = 0.0f;

        #pragma unroll 4
        for (int u = 0; u < 32; ++u) {
            float4 xv = xp[u * 4 + h];
            int cc = u * 16 + h * 4;
            #pragma unroll
            for (int l = 0; l < LCLS; ++l) {
                float4 sv = *(const float4*)&SEM[l * CDIM + cc];
                s3[l] += xv.x * sv.x + xv.y * sv.y + xv.z * sv.z + xv.w * sv.w;
            }
            // produce bf16 split pairs for GEMM1
            float vf[4] = {xv.x, xv.y, xv.z, xv.w};
            float hi[4], lo[4];
            #pragma unroll
            for (int e = 0; e < 4; ++e) {
                __nv_bfloat16 b = __float2bfloat16(vf[e]);
                hi[e] = __bfloat162float(b);
                lo[e] = vf[e] - hi[e];
            }
            uint4 o;
            o.x = pack_bf16(hi[0], hi[1]);
            o.y = pack_bf16(lo[0], lo[1]);
            o.z = pack_bf16(hi[2], hi[3]);
            o.w = pack_bf16(lo[2], lo[3]);
            xi[u * 4 + h] = o;
        }
        #pragma unroll
        for (int l = 0; l < LCLS; ++l) {
            s3[l] += __shfl_xor_sync(0xffffffffu, s3[l], 1);
            s3[l] += __shfl_xor_sync(0xffffffffu, s3[l], 2);
        }

        float mx = s3[0];
        #pragma unroll
        for (int l = 1; l < LCLS; ++l) mx = fmaxf(mx, s3[l]);
        float se = 0.0f;
        #pragma unroll
        for (int l = 0; l < LCLS; ++l) { s3[l] = __expf(s3[l] - mx); se += s3[l]; }
        float inv = 1.0f / se;
        float l1 = 0.0f;
        #pragma unroll
        for (int l = 0; l < LCLS; ++l) {
            float a = s3[l] * inv;
            float t = a - SHRINK_L;
            float v = fmaxf(t, 0.0f) * a / (fabsf(t) + EPS_F);
            s3[l] = v; l1 += v;
        }
        float sc = 1.0f / fmaxf(l1, EPS_F);
        #pragma unroll
        for (int l = 0; l < LCLS; ++l) s3[l] *= sc;
        if (h == 0) {
            #pragma unroll
            for (int l = 0; l < LCLS; ++l)
                out_att[(size_t)(rowbase + r) * LCLS + l] = s3[l];
        }
        float4* op = (float4*)(out_sem + (size_t)(rowbase + r) * CDIM);
        #pragma unroll 4
        for (int u = 0; u < 32; ++u) {
            int cc = u * 16 + h * 4;
            float4 acc = make_float4(0.f, 0.f, 0.f, 0.f);
            #pragma unroll
            for (int l = 0; l < LCLS; ++l) {
                float4 sv = *(const float4*)&SEM[l * CDIM + cc];
                acc.x += s3[l] * sv.x; acc.y += s3[l] * sv.y;
                acc.z += s3[l] * sv.z; acc.w += s3[l] * sv.w;
            }
            op[u * 4 + h] = acc;
        }
        __syncthreads();   // SEM dead; g_Xi writes visible to CTA
    }

    const int wm = wid >> 1;          // 0..3 (M tile)
    const int wn = wid & 1;           // 0..1 (N half)
    const int qr = lane >> 2;         // 0..7
    const int q  = lane & 3;          // 0..3
    const int row = wm * 16 + qr;

    // ====================== GEMM1: logits [64,320] ==========================
    float acc[20][4];
    {
        #pragma unroll
        for (int j = 0; j < 20; ++j)
            #pragma unroll
            for (int e = 0; e < 4; ++e) acc[j][e] = 0.0f;

        const u64* xr0 = g_Xi + (size_t)(rowbase + row) * 256;
        const u64* xr1 = xr0 + 8 * 256;

        // prologue: fill stages 0,1 (ks=0,1)
        #pragma unroll
        for (int s = 0; s < 2; ++s) {
            #pragma unroll
            for (int it = 0; it < 5; ++it) {
                int i = tid + it * 256;
                int nt = i >> 5;
                cp16(sb + OFF_G1 + (u32)(s * ST1 + i * 16),
                     &g_B1[nt * 1024 + s * 32 + (i & 31)]);
            }
            CP_COMMIT();
        }
        // prefetch A for ks=0
        u64 nA0 = xr0[q], nA1 = xr1[q], nA2 = xr0[q + 4], nA3 = xr1[q + 4];

        for (int ks = 0; ks < 32; ++ks) {
            if (ks >= 30) { CP_WAIT0(); } else { CP_WAIT1(); }
            __syncthreads();
            if (ks + 2 < 32) {
                int ks2 = ks + 2, stg2 = ks2 % 3;
                #pragma unroll
                for (int it = 0; it < 5; ++it) {
                    int i = tid + it * 256;
                    int nt = i >> 5;
                    cp16(sb + OFF_G1 + (u32)(stg2 * ST1 + i * 16),
                         &g_B1[nt * 1024 + ks2 * 32 + (i & 31)]);
                }
                CP_COMMIT();
            }
            u64 A0 = nA0, A1 = nA1, A2 = nA2, A3 = nA3;
            if (ks < 31) {
                int kp = (ks + 1) * 8 + q;
                nA0 = xr0[kp]; nA1 = xr1[kp]; nA2 = xr0[kp + 4]; nA3 = xr1[kp + 4];
            }
            u32 x1a0 = (u32)A0, x2a0 = (u32)(A0 >> 32);
            u32 x1a1 = (u32)A1, x2a1 = (u32)(A1 >> 32);
            u32 x1a2 = (u32)A2, x2a2 = (u32)(A2 >> 32);
            u32 x1a3 = (u32)A3, x2a3 = (u32)(A3 >> 32);
            const uint4* bp = (const uint4*)(smem + OFF_G1 + (ks % 3) * ST1)
                              + wn * 640 + lane;
            #pragma unroll
            for (int j = 0; j < 20; ++j) {
                uint4 B = bp[j * 32];
                hmma(acc[j], x1a0, x1a1, x1a2, x1a3, B.x, B.y);
                hmma(acc[j], x1a0, x1a1, x1a2, x1a3, B.z, B.w);
                hmma(acc[j], x2a0, x2a1, x2a2, x2a3, B.x, B.y);
            }
        }
        __syncthreads();
    }

    // ============ softmax-320 / shrink / bf16-split (from regs) =============
    float* RED0 = (float*)(smem + OFF_RED);          // [2][64] max
    float* RED1 = RED0 + 128;                         // [2][64] expsum
    float* RED2 = RED1 + 128;                         // [2][64] l1
    {
        // round 1: row max
        float m0 = -1e30f, m1 = -1e30f;
        #pragma unroll
        for (int j = 0; j < 20; ++j) {
            m0 = fmaxf(m0, fmaxf(acc[j][0], acc[j][1]));
            m1 = fmaxf(m1, fmaxf(acc[j][2], acc[j][3]));
        }
        m0 = fmaxf(m0, __shfl_xor_sync(0xffffffffu, m0, 1));
        m0 = fmaxf(m0, __shfl_xor_sync(0xffffffffu, m0, 2));
        m1 = fmaxf(m1, __shfl_xor_sync(0xffffffffu, m1, 1));
        m1 = fmaxf(m1, __shfl_xor_sync(0xffffffffu, m1, 2));
        if (q == 0) { RED0[wn * 64 + row] = m0; RED0[wn * 64 + row + 8] = m1; }
        __syncthreads();
        float M0 = fmaxf(RED0[row],     RED0[64 + row]);
        float M1 = fmaxf(RED0[row + 8], RED0[64 + row + 8]);

        // round 2: exp + expsum
        float s0 = 0.0f, s1 = 0.0f;
        #pragma unroll
        for (int j = 0; j < 20; ++j) {
            acc[j][0] = __expf(acc[j][0] - M0);
            acc[j][1] = __expf(acc[j][1] - M0);
            acc[j][2] = __expf(acc[j][2] - M1);
            acc[j][3] = __expf(acc[j][3] - M1);
            s0 += acc[j][0] + acc[j][1];
            s1 += acc[j][2] + acc[j][3];
        }
        s0 += __shfl_xor_sync(0xffffffffu, s0, 1);
        s0 += __shfl_xor_sync(0xffffffffu, s0, 2);
        s1 += __shfl_xor_sync(0xffffffffu, s1, 1);
        s1 += __shfl_xor_sync(0xffffffffu, s1, 2);
        if (q == 0) { RED1[wn * 64 + row] = s0; RED1[wn * 64 + row + 8] = s1; }
        __syncthreads();
        float inv0 = 1.0f / (RED1[row]     + RED1[64 + row]);
        float inv1 = 1.0f / (RED1[row + 8] + RED1[64 + row + 8]);

        // round 3: shrink, l1, store T1/T2 frags
        float l10 = 0.0f, l11 = 0.0f;
        u32* T1 = (u32*)(smem + OFF_T1);
        u32* T2 = (u32*)(smem + OFF_T2);
        #pragma unroll
        for (int j = 0; j < 20; ++j) {
            int col = wn * 160 + j * 8 + 2 * q;
            float a0 = acc[j][0] * inv0, a1 = acc[j][1] * inv0;
            float a2 = acc[j][2] * inv1, a3 = acc[j][3] * inv1;
            float t0 = a0 - SHRINK_L, t1 = a1 - SHRINK_L;
            float t2 = a2 - SHRINK_L, t3 = a3 - SHRINK_L;
            float v0 = fmaxf(t0, 0.0f) * a0 / (fabsf(t0) + EPS_F);
            float v1 = fmaxf(t1, 0.0f) * a1 / (fabsf(t1) + EPS_F);
            float v2 = fmaxf(t2, 0.0f) * a2 / (fabsf(t2) + EPS_F);
            float v3 = fmaxf(t3, 0.0f) * a3 / (fabsf(t3) + EPS_F);
            l10 += v0 + v1; l11 += v2 + v3;
            __nv_bfloat16 b0 = __float2bfloat16(v0), b1 = __float2bfloat16(v1);
            __nv_bfloat16 b2 = __float2bfloat16(v2), b3 = __float2bfloat16(v3);
            float h0 = __bfloat162float(b0), h1 = __bfloat162float(b1);
            float h2 = __bfloat162float(b2), h3 = __bfloat162float(b3);
            int w0 = (row * LSTR + col) >> 1;
            int w1 = ((row + 8) * LSTR + col) >> 1;
            T1[w0] = pack_bf16(h0, h1);
            T1[w1] = pack_bf16(h2, h3);
            T2[w0] = pack_bf16(v0 - h0, v1 - h1);
            T2[w1] = pack_bf16(v2 - h2, v3 - h3);
        }
        l10 += __shfl_xor_sync(0xffffffffu, l10, 1);
        l10 += __shfl_xor_sync(0xffffffffu, l10, 2);
        l11 += __shfl_xor_sync(0xffffffffu, l11, 1);
        l11 += __shfl_xor_sync(0xffffffffu, l11, 2);
        if (q == 0) { RED2[wn * 64 + row] = l10; RED2[wn * 64 + row + 8] = l11; }
        __syncthreads();
    }
    const float sc0 = 1.0f / fmaxf(RED2[row]     + RED2[64 + row],     EPS_F);
    const float sc1 = 1.0f / fmaxf(RED2[row + 8] + RED2[64 + row + 8], EPS_F);
    __syncthreads();   // all RED reads done before the G2 ring reuses that space

    // ================ GEMM2: out_part [64,512], flattened ===================
    {
        // prologue: fill stages 0,1 (s=0,1 -> hh=0, ks=0,1)
        #pragma unroll
        for (int s = 0; s < 2; ++s) {
            #pragma unroll
            for (int it = 0; it < 4; ++it) {
                int i = tid + it * 256;
                int jj = i >> 5;
                cp16(sb + OFF_G2 + (u32)(s * ST2 + i * 16),
                     &g_B2[jj * 640 + s * 32 + (i & 31)]);
            }
            CP_COMMIT();
        }

        float acc2[16][4];
        for (int s = 0; s < 40; ++s) {
            int hh = s / 20, ks = s % 20;
            if (ks == 0) {
                #pragma unroll
                for (int j = 0; j < 16; ++j)
                    #pragma unroll
                    for (int e = 0; e < 4; ++e) acc2[j][e] = 0.0f;
            }
            if (s >= 38) { CP_WAIT0(); } else { CP_WAIT1(); }
            __syncthreads();

            int kb = ks * 16 + 2 * q;
            const u32* T1 = (const u32*)(smem + OFF_T1);
            const u32* T2 = (const u32*)(smem + OFF_T2);
            u32 a10 = T1[(row * LSTR + kb) >> 1];
            u32 a11 = T1[((row + 8) * LSTR + kb) >> 1];
            u32 a12 = T1[(row * LSTR + kb + 8) >> 1];
            u32 a13 = T1[((row + 8) * LSTR + kb + 8) >> 1];
            u32 a20 = T2[(row * LSTR + kb) >> 1];
            u32 a21 = T2[((row + 8) * LSTR + kb) >> 1];
            u32 a22 = T2[(row * LSTR + kb + 8) >> 1];
            u32 a23 = T2[((row + 8) * LSTR + kb + 8) >> 1];
            const uint4* bp = (const uint4*)(smem + OFF_G2 + (s & 1) * ST2)
                              + wn * 512 + lane;
            #pragma unroll
            for (int j = 0; j < 16; ++j) {
                uint4 B = bp[j * 32];
                hmma(acc2[j], a10, a11, a12, a13, B.x, B.y);
                hmma(acc2[j], a10, a11, a12, a13, B.z, B.w);
                hmma(acc2[j], a20, a21, a22, a23, B.x, B.y);
            }

            if (ks == 19) {
                size_t gr = (size_t)(rowbase + row);
                #pragma unroll
                for (int j = 0; j < 16; ++j) {
                    int col = hh * 256 + wn * 128 + j * 8 + 2 * q;
                    float2 p0; p0.x = acc2[j][0] * sc0; p0.y = acc2[j][1] * sc0;
                    float2 p1; p1.x = acc2[j][2] * sc1; p1.y = acc2[j][3] * sc1;
                    *(float2*)(out_part + gr * CDIM + col)       = p0;
                    *(float2*)(out_part + (gr + 8) * CDIM + col) = p1;
                }
            }

            if (s + 2 < 40) {
                __syncthreads();   // everyone done reading stage s&1 before refill
                int s2 = s + 2;
                int hh2 = s2 / 20, ks2 = s2 % 20;
                #pragma unroll
                for (int it = 0; it < 4; ++it) {
                    int i = tid + it * 256;
                    int jj = i >> 5;
                    cp16(sb + OFF_G2 + (u32)((s & 1) * ST2 + i * 16),
                         &g_B2[(hh2 * 32 + jj) * 640 + ks2 * 32 + (i & 31)]);
                }
                CP_COMMIT();
            }
        }
    }
}

// ---------------------------------------------------------------------------
extern "C" void kernel_launch(void* const* d_in, const int* in_sizes, int n_in,
                              void* d_out, int out_size) {
    const float* X  = (const float*)d_in[0];
    const float* W  = (const float*)d_in[1];
    const float* wp = (const float*)d_in[2];
    const float* bp = (const float*)d_in[3];
    const float* wi = (const float*)d_in[4];
    const float* bi = (const float*)d_in[5];

    int N = in_sizes[0] / CDIM;   // 131072

    float* out      = (float*)d_out;
    float* out_sem  = out;                                   // [N, 512]
    float* out_att  = out + (size_t)N * CDIM;                // [N, 10]
    float* out_semm = out_att + (size_t)N * LCLS;            // [10, 512]
    float* out_part = out_semm + (size_t)LCLS * CDIM;        // [N, 512]

    sem_build_kernel<<<1, 512>>>(W, wp, bp, wi, bi, out_semm);
    bfrag1_kernel<<<(40 * 32 * 32 + 255) / 256, 256>>>(W);
    bfrag2_kernel<<<(64 * 20 * 32 + 255) / 256, 256>>>(W);

    cudaFuncSetAttribute(fused_kernel,
                         cudaFuncAttributeMaxDynamicSharedMemorySize, SMEM_BYTES);
    fused_kernel<<<N / BM, THREADS, SMEM_BYTES>>>(X, out_sem, out_att, out_part);
}

// round 17
// speedup vs baseline: 3.5326x; 1.0234x over previous
#include <cuda_runtime.h>
#include <cuda_bf16.h>

typedef unsigned int u32;
typedef unsigned long long u64;

#define CDIM 512
#define MDIM 320
#define LCLS 10
#define SHRINK_L 0.0025f
#define EPS_F 1e-12f
#define BM 64
#define THREADS 256
#define NMAX 131072

// ---- shared memory byte offsets (phase overlap, 2 CTAs/SM) ----
// SEM [0,20480)        phase A only
// G1 ring [0,61440)    GEMM1 only (3 x 20480)
// T1 [0,40960) T2 [40960,81920)   written by epilogue, read by GEMM2
// RED [81920,+3072)    epilogue only (read out before G2 fill)
// G2 ring [81920,114688)  2 x 16384
#define OFF_SEM  0
#define OFF_T1   0
#define OFF_T2   40960
#define OFF_G1   0
#define ST1      20480
#define OFF_RED  81920
#define OFF_G2   81920
#define ST2      16384
#define SMEM_BYTES 114688

// T word index: row*160 + (cw ^ 4*(row&7)), cw = col/2 in [0,160)
__device__ __forceinline__ int t_word(int row, int cw, int qr) {
    return row * 160 + (cw ^ (qr << 2));
}

// ---- global scratch ----
__device__ u64  g_Xi[(size_t)NMAX * 256];   // {x1 pair, x2 pair} per 2 cols (written in-kernel)
__device__ uint4 g_B1[40 * 32 * 32];        // GEMM1 B frags [nt][ks][lane]
__device__ uint4 g_B2[64 * 20 * 32];        // GEMM2 B frags [nt][ks][lane]
__device__ float g_sem[LCLS * CDIM];

__device__ __forceinline__ float sigmoidf_(float x) { return 1.0f / (1.0f + __expf(-x)); }

__device__ __forceinline__ u32 pack_bf16(float lo, float hi) {
    __nv_bfloat162 h2 = __floats2bfloat162_rn(lo, hi);
    return *reinterpret_cast<u32*>(&h2);
}

__device__ __forceinline__ u32 smem_u32(const void* p) {
    u32 a;
    asm("{ .reg .u64 t; cvta.to.shared.u64 t, %1; cvt.u32.u64 %0, t; }" : "=r"(a) : "l"(p));
    return a;
}

__device__ __forceinline__ void cp16(u32 dst, const void* src) {
    asm volatile("cp.async.cg.shared.global [%0], [%1], 16;" :: "r"(dst), "l"(src) : "memory");
}
#define CP_COMMIT() asm volatile("cp.async.commit_group;" ::: "memory")
#define CP_WAIT0()  asm volatile("cp.async.wait_group 0;" ::: "memory")
#define CP_WAIT1()  asm volatile("cp.async.wait_group 1;" ::: "memory")

__device__ __forceinline__ void hmma(float* c, u32 a0, u32 a1, u32 a2, u32 a3,
                                     u32 b0, u32 b1) {
    asm volatile(
        "mma.sync.aligned.m16n8k16.row.col.f32.bf16.bf16.f32 "
        "{%0,%1,%2,%3}, {%4,%5,%6,%7}, {%8,%9}, {%0,%1,%2,%3};"
        : "+f"(c[0]), "+f"(c[1]), "+f"(c[2]), "+f"(c[3])
        : "r"(a0), "r"(a1), "r"(a2), "r"(a3), "r"(b0), "r"(b1));
}

// ---------------------------------------------------------------------------
// Prologue 1: sem_att build
// ---------------------------------------------------------------------------
__global__ void sem_build_kernel(const float* __restrict__ W,
                                 const float* __restrict__ wp,
                                 const float* __restrict__ bp,
                                 const float* __restrict__ wi,
                                 const float* __restrict__ bi,
                                 float* __restrict__ out_semmat) {
    int c = threadIdx.x;
    if (c >= CDIM) return;
    float wpl[16], bpl[4], wil[64], bil[8];
    #pragma unroll
    for (int i = 0; i < 16; ++i) wpl[i] = wp[i];
    #pragma unroll
    for (int i = 0; i < 4; ++i) bpl[i] = bp[i];
    #pragma unroll
    for (int i = 0; i < 64; ++i) wil[i] = wi[i];
    #pragma unroll
    for (int i = 0; i < 8; ++i) bil[i] = bi[i];

    for (int l = 0; l < LCLS; ++l) {
        float pt[8];
        #pragma unroll
        for (int t = 0; t < 8; ++t) {
            int n = l * 8 + t;
            float4 r4 = *(const float4*)(W + n * 2048 + c * 4);
            float rp[4] = {r4.x, r4.y, r4.z, r4.w};
            float acc = 0.0f;
            #pragma unroll
            for (int qq = 0; qq < 4; ++qq) {
                float s = bpl[qq];
                #pragma unroll
                for (int p = 0; p < 4; ++p) s += wpl[qq * 4 + p] * rp[p];
                acc += sigmoidf_(s) * rp[qq];
            }
            pt[t] = acc * 0.25f;
        }
        float acc2 = 0.0f;
        #pragma unroll
        for (int qq = 0; qq < 8; ++qq) {
            float s = bil[qq];
            #pragma unroll
            for (int t = 0; t < 8; ++t) s += wil[qq * 8 + t] * pt[t];
            acc2 += sigmoidf_(s) * pt[qq];
        }
        float v = acc2 * 0.125f;
        g_sem[l * CDIM + c] = v;
        out_semmat[l * CDIM + c] = v;
    }
}

// ---------------------------------------------------------------------------
// Prologue 2: W fragments for GEMM1 (B = W^T)
// ---------------------------------------------------------------------------
__global__ void bfrag1_kernel(const float* __restrict__ W) {
    int idx = blockIdx.x * 256 + threadIdx.x;
    if (idx >= 40 * 32 * 32) return;
    int nt = idx >> 10, ks = (idx >> 5) & 31, l = idx & 31;
    int n = nt * 8 + (l >> 2);
    int kb = ks * 16 + 2 * (l & 3);
    float v[4] = { W[n * CDIM + kb], W[n * CDIM + kb + 1],
                   W[n * CDIM + kb + 8], W[n * CDIM + kb + 9] };
    float h[4], r[4];
    #pragma unroll
    for (int e = 0; e < 4; ++e) {
        __nv_bfloat16 b = __float2bfloat16(v[e]);
        h[e] = __bfloat162float(b);
        r[e] = v[e] - h[e];
    }
    uint4 o;
    o.x = pack_bf16(h[0], h[1]);
    o.y = pack_bf16(h[2], h[3]);
    o.z = pack_bf16(r[0], r[1]);
    o.w = pack_bf16(r[2], r[3]);
    g_B1[idx] = o;
}

// ---------------------------------------------------------------------------
// Prologue 3: W fragments for GEMM2 (B = W)
// ---------------------------------------------------------------------------
__global__ void bfrag2_kernel(const float* __restrict__ W) {
    int idx = blockIdx.x * 256 + threadIdx.x;
    if (idx >= 64 * 20 * 32) return;
    int nt = idx / 640, rem = idx % 640;
    int ks = rem >> 5, l = rem & 31;
    int n = nt * 8 + (l >> 2);
    int kb = ks * 16 + 2 * (l & 3);
    float v[4] = { W[kb * CDIM + n], W[(kb + 1) * CDIM + n],
                   W[(kb + 8) * CDIM + n], W[(kb + 9) * CDIM + n] };
    float h[4], r[4];
    #pragma unroll
    for (int e = 0; e < 4; ++e) {
        __nv_bfloat16 b = __float2bfloat16(v[e]);
        h[e] = __bfloat162float(b);
        r[e] = v[e] - h[e];
    }
    uint4 o;
    o.x = pack_bf16(h[0], h[1]);
    o.y = pack_bf16(h[2], h[3]);
    o.z = pack_bf16(r[0], r[1]);
    o.w = pack_bf16(r[2], r[3]);
    g_B2[idx] = o;
}

// ---------------------------------------------------------------------------
// Main fused kernel (2 CTAs / SM). Warp tiling: wm2 in {0,1} = 32 rows,
// wn2 in {0..3} = N quarter.
// ---------------------------------------------------------------------------
__global__ __launch_bounds__(THREADS, 2)
void fused_kernel(const float* __restrict__ X,
                  float* __restrict__ out_sem,
                  float* __restrict__ out_att,
                  float* __restrict__ out_part) {
    extern __shared__ char smem[];
    const u32 sb = smem_u32(smem);
    const int tid = threadIdx.x;
    const int wid = tid >> 5;
    const int lane = tid & 31;
    const int rowbase = blockIdx.x * BM;

    // ============ Phase A: stage-3 attend + produce g_Xi splits =============
    {
        float* SEM = (float*)(smem + OFF_SEM);
        for (int i = tid; i < LCLS * CDIM / 4; i += THREADS)
            ((float4*)SEM)[i] = ((const float4*)g_sem)[i];
        __syncthreads();

        const int r = tid >> 2, h = tid & 3;
        const float4* xp = (const float4*)(X + (size_t)(rowbase + r) * CDIM);
        uint4* xi = ((uint4*)g_Xi) + (size_t)(rowbase + r) * 128;
        float s3[LCLS];
        #pragma unroll
        for (int l = 0; l < LCLS; ++l) s3[l] = 0.0f;

        #pragma unroll 4
        for (int u = 0; u < 32; ++u) {
            float4 xv = xp[u * 4 + h];
            int cc = u * 16 + h * 4;
            #pragma unroll
            for (int l = 0; l < LCLS; ++l) {
                float4 sv = *(const float4*)&SEM[l * CDIM + cc];
                s3[l] += xv.x * sv.x + xv.y * sv.y + xv.z * sv.z + xv.w * sv.w;
            }
            float vf[4] = {xv.x, xv.y, xv.z, xv.w};
            float hi[4], lo[4];
            #pragma unroll
            for (int e = 0; e < 4; ++e) {
                __nv_bfloat16 b = __float2bfloat16(vf[e]);
                hi[e] = __bfloat162float(b);
                lo[e] = vf[e] - hi[e];
            }
            uint4 o;
            o.x = pack_bf16(hi[0], hi[1]);
            o.y = pack_bf16(lo[0], lo[1]);
            o.z = pack_bf16(hi[2], hi[3]);
            o.w = pack_bf16(lo[2], lo[3]);
            xi[u * 4 + h] = o;
        }
        #pragma unroll
        for (int l = 0; l < LCLS; ++l) {
            s3[l] += __shfl_xor_sync(0xffffffffu, s3[l], 1);
            s3[l] += __shfl_xor_sync(0xffffffffu, s3[l], 2);
        }

        float mx = s3[0];
        #pragma unroll
        for (int l = 1; l < LCLS; ++l) mx = fmaxf(mx, s3[l]);
        float se = 0.0f;
        #pragma unroll
        for (int l = 0; l < LCLS; ++l) { s3[l] = __expf(s3[l] - mx); se += s3[l]; }
        float inv = 1.0f / se;
        float l1 = 0.0f;
        #pragma unroll
        for (int l = 0; l < LCLS; ++l) {
            float a = s3[l] * inv;
            float t = a - SHRINK_L;
            float v = fmaxf(t, 0.0f) * a / (fabsf(t) + EPS_F);
            s3[l] = v; l1 += v;
        }
        float sc = 1.0f / fmaxf(l1, EPS_F);
        #pragma unroll
        for (int l = 0; l < LCLS; ++l) s3[l] *= sc;
        if (h == 0) {
            #pragma unroll
            for (int l = 0; l < LCLS; ++l)
                out_att[(size_t)(rowbase + r) * LCLS + l] = s3[l];
        }
        float4* op = (float4*)(out_sem + (size_t)(rowbase + r) * CDIM);
        #pragma unroll 4
        for (int u = 0; u < 32; ++u) {
            int cc = u * 16 + h * 4;
            float4 acc = make_float4(0.f, 0.f, 0.f, 0.f);
            #pragma unroll
            for (int l = 0; l < LCLS; ++l) {
                float4 sv = *(const float4*)&SEM[l * CDIM + cc];
                acc.x += s3[l] * sv.x; acc.y += s3[l] * sv.y;
                acc.z += s3[l] * sv.z; acc.w += s3[l] * sv.w;
            }
            op[u * 4 + h] = acc;
        }
        __syncthreads();
    }

    const int wm2 = wid >> 2;         // 0..1 : 32-row tile
    const int wn2 = wid & 3;          // 0..3 : N quarter
    const int qr = lane >> 2;         // 0..7
    const int q  = lane & 3;          // 0..3
    const int r0 = wm2 * 32 + qr;     // rows r0, r0+8, r0+16, r0+24

    // ====================== GEMM1: logits [64,320] ==========================
    float acc[10][8];
    {
        #pragma unroll
        for (int j = 0; j < 10; ++j)
            #pragma unroll
            for (int e = 0; e < 8; ++e) acc[j][e] = 0.0f;

        const u64* xa = g_Xi + (size_t)(rowbase + r0) * 256;
        const u64* xb = xa + 8 * 256;
        const u64* xc = xa + 16 * 256;
        const u64* xd = xa + 24 * 256;

        // prologue: fill stages 0,1
        #pragma unroll
        for (int s = 0; s < 2; ++s) {
            #pragma unroll
            for (int it = 0; it < 5; ++it) {
                int i = tid + it * 256;
                int nt = i >> 5;
                cp16(sb + OFF_G1 + (u32)(s * ST1 + i * 16),
                     &g_B1[nt * 1024 + s * 32 + (i & 31)]);
            }
            CP_COMMIT();
        }
        // prefetch A for ks=0
        u64 nA[8] = { xa[q], xb[q], xa[q + 4], xb[q + 4],
                      xc[q], xd[q], xc[q + 4], xd[q + 4] };

        for (int ks = 0; ks < 32; ++ks) {
            if (ks >= 30) { CP_WAIT0(); } else { CP_WAIT1(); }
            __syncthreads();
            if (ks + 2 < 32) {
                int ks2 = ks + 2, stg2 = ks2 % 3;
                #pragma unroll
                for (int it = 0; it < 5; ++it) {
                    int i = tid + it * 256;
                    int nt = i >> 5;
                    cp16(sb + OFF_G1 + (u32)(stg2 * ST1 + i * 16),
                         &g_B1[nt * 1024 + ks2 * 32 + (i & 31)]);
                }
                CP_COMMIT();
            }
            u64 A[8];
            #pragma unroll
            for (int e = 0; e < 8; ++e) A[e] = nA[e];
            if (ks < 31) {
                int kp = (ks + 1) * 8 + q;
                nA[0] = xa[kp]; nA[1] = xb[kp]; nA[2] = xa[kp + 4]; nA[3] = xb[kp + 4];
                nA[4] = xc[kp]; nA[5] = xd[kp]; nA[6] = xc[kp + 4]; nA[7] = xd[kp + 4];
            }
            u32 p1[4], p2[4], r1[4], r2[4];
            #pragma unroll
            for (int e = 0; e < 4; ++e) {
                p1[e] = (u32)A[e];     p2[e] = (u32)(A[e] >> 32);
                r1[e] = (u32)A[4 + e]; r2[e] = (u32)(A[4 + e] >> 32);
            }
            const uint4* bp = (const uint4*)(smem + OFF_G1 + (ks % 3) * ST1)
                              + wn2 * 320 + lane;
            #pragma unroll
            for (int j = 0; j < 10; ++j) {
                uint4 B = bp[j * 32];
                hmma(acc[j],     p1[0], p1[1], p1[2], p1[3], B.x, B.y);
                hmma(acc[j],     p1[0], p1[1], p1[2], p1[3], B.z, B.w);
                hmma(acc[j],     p2[0], p2[1], p2[2], p2[3], B.x, B.y);
                hmma(acc[j] + 4, r1[0], r1[1], r1[2], r1[3], B.x, B.y);
                hmma(acc[j] + 4, r1[0], r1[1], r1[2], r1[3], B.z, B.w);
                hmma(acc[j] + 4, r2[0], r2[1], r2[2], r2[3], B.x, B.y);
            }
        }
        __syncthreads();
    }

    // ============ softmax-320 / shrink / bf16-split (from regs) =============
    // rows owned: r0, r0+8 (e 0..3), r0+16, r0+24 (e 4..7)
    float* RED0 = (float*)(smem + OFF_RED);          // [4][64] max
    float* RED1 = RED0 + 256;                         // [4][64] expsum
    float* RED2 = RED1 + 256;                         // [4][64] l1
    float scv[4];
    {
        float m[4] = {-1e30f, -1e30f, -1e30f, -1e30f};
        #pragma unroll
        for (int j = 0; j < 10; ++j) {
            #pragma unroll
            for (int e = 0; e < 4; ++e)
                m[e] = fmaxf(m[e], fmaxf(acc[j][2 * e], acc[j][2 * e + 1]));
        }
        #pragma unroll
        for (int e = 0; e < 4; ++e) {
            m[e] = fmaxf(m[e], __shfl_xor_sync(0xffffffffu, m[e], 1));
            m[e] = fmaxf(m[e], __shfl_xor_sync(0xffffffffu, m[e], 2));
        }
        if (q == 0) {
            #pragma unroll
            for (int e = 0; e < 4; ++e)
                RED0[wn2 * 64 + r0 + e * 8] = m[e];
        }
        __syncthreads();
        float M[4];
        #pragma unroll
        for (int e = 0; e < 4; ++e) {
            int rr = r0 + e * 8;
            M[e] = fmaxf(fmaxf(RED0[rr], RED0[64 + rr]),
                         fmaxf(RED0[128 + rr], RED0[192 + rr]));
        }

        float s[4] = {0.f, 0.f, 0.f, 0.f};
        #pragma unroll
        for (int j = 0; j < 10; ++j) {
            #pragma unroll
            for (int e = 0; e < 4; ++e) {
                acc[j][2 * e]     = __expf(acc[j][2 * e]     - M[e]);
                acc[j][2 * e + 1] = __expf(acc[j][2 * e + 1] - M[e]);
                s[e] += acc[j][2 * e] + acc[j][2 * e + 1];
            }
        }
        #pragma unroll
        for (int e = 0; e < 4; ++e) {
            s[e] += __shfl_xor_sync(0xffffffffu, s[e], 1);
            s[e] += __shfl_xor_sync(0xffffffffu, s[e], 2);
        }
        if (q == 0) {
            #pragma unroll
            for (int e = 0; e < 4; ++e)
                RED1[wn2 * 64 + r0 + e * 8] = s[e];
        }
        __syncthreads();
        float inv[4];
        #pragma unroll
        for (int e = 0; e < 4; ++e) {
            int rr = r0 + e * 8;
            inv[e] = 1.0f / (RED1[rr] + RED1[64 + rr] + RED1[128 + rr] + RED1[192 + rr]);
        }

        float l1[4] = {0.f, 0.f, 0.f, 0.f};
        u32* T1 = (u32*)(smem + OFF_T1);
        u32* T2 = (u32*)(smem + OFF_T2);
        #pragma unroll
        for (int j = 0; j < 10; ++j) {
            int cw = wn2 * 40 + j * 4 + q;
            #pragma unroll
            for (int e = 0; e < 4; ++e) {
                float a0 = acc[j][2 * e] * inv[e];
                float a1 = acc[j][2 * e + 1] * inv[e];
                float t0 = a0 - SHRINK_L, t1 = a1 - SHRINK_L;
                float v0 = fmaxf(t0, 0.0f) * a0 / (fabsf(t0) + EPS_F);
                float v1 = fmaxf(t1, 0.0f) * a1 / (fabsf(t1) + EPS_F);
                l1[e] += v0 + v1;
                __nv_bfloat16 b0 = __float2bfloat16(v0), b1 = __float2bfloat16(v1);
                float h0 = __bfloat162float(b0), h1 = __bfloat162float(b1);
                int w = t_word(r0 + e * 8, cw, qr);
                T1[w] = pack_bf16(h0, h1);
                T2[w] = pack_bf16(v0 - h0, v1 - h1);
            }
        }
        #pragma unroll
        for (int e = 0; e < 4; ++e) {
            l1[e] += __shfl_xor_sync(0xffffffffu, l1[e], 1);
            l1[e] += __shfl_xor_sync(0xffffffffu, l1[e], 2);
        }
        if (q == 0) {
            #pragma unroll
            for (int e = 0; e < 4; ++e)
                RED2[wn2 * 64 + r0 + e * 8] = l1[e];
        }
        __syncthreads();
        #pragma unroll
        for (int e = 0; e < 4; ++e) {
            int rr = r0 + e * 8;
            scv[e] = 1.0f / fmaxf(RED2[rr] + RED2[64 + rr] + RED2[128 + rr] + RED2[192 + rr],
                                  EPS_F);
        }
    }
    __syncthreads();   // all RED reads done before the G2 ring reuses that space

    // ================ GEMM2: out_part [64,512], flattened ===================
    {
        // prologue: fill stages 0,1 (s=0,1 -> hh=0, ks=0,1)
        #pragma unroll
        for (int s = 0; s < 2; ++s) {
            #pragma unroll
            for (int it = 0; it < 4; ++it) {
                int i = tid + it * 256;
                int jj = i >> 5;
                cp16(sb + OFF_G2 + (u32)(s * ST2 + i * 16),
                     &g_B2[jj * 640 + s * 32 + (i & 31)]);
            }
            CP_COMMIT();
        }

        float acc2[8][8];
        for (int s = 0; s < 40; ++s) {
            int hh = s / 20, ks = s % 20;
            if (ks == 0) {
                #pragma unroll
                for (int j = 0; j < 8; ++j)
                    #pragma unroll
                    for (int e = 0; e < 8; ++e) acc2[j][e] = 0.0f;
            }
            if (s >= 38) { CP_WAIT0(); } else { CP_WAIT1(); }
            __syncthreads();

            int cw = ks * 8 + q;
            const u32* T1 = (const u32*)(smem + OFF_T1);
            const u32* T2 = (const u32*)(smem + OFF_T2);
            u32 a1f[8], a2f[8];   // [mt*4 + {0,1,2,3}] = rows (2mt,2mt+1) x (cw,cw+4)
            #pragma unroll
            for (int mt = 0; mt < 2; ++mt) {
                int ra = r0 + mt * 16, rb = ra + 8;
                a1f[mt * 4 + 0] = T1[t_word(ra, cw, qr)];
                a1f[mt * 4 + 1] = T1[t_word(rb, cw, qr)];
                a1f[mt * 4 + 2] = T1[t_word(ra, cw + 4, qr)];
                a1f[mt * 4 + 3] = T1[t_word(rb, cw + 4, qr)];
                a2f[mt * 4 + 0] = T2[t_word(ra, cw, qr)];
                a2f[mt * 4 + 1] = T2[t_word(rb, cw, qr)];
                a2f[mt * 4 + 2] = T2[t_word(ra, cw + 4, qr)];
                a2f[mt * 4 + 3] = T2[t_word(rb, cw + 4, qr)];
            }
            const uint4* bp = (const uint4*)(smem + OFF_G2 + (s & 1) * ST2)
                              + wn2 * 256 + lane;
            #pragma unroll
            for (int j = 0; j < 8; ++j) {
                uint4 B = bp[j * 32];
                hmma(acc2[j],     a1f[0], a1f[1], a1f[2], a1f[3], B.x, B.y);
                hmma(acc2[j],     a1f[0], a1f[1], a1f[2], a1f[3], B.z, B.w);
                hmma(acc2[j],     a2f[0], a2f[1], a2f[2], a2f[3], B.x, B.y);
                hmma(acc2[j] + 4, a1f[4], a1f[5], a1f[6], a1f[7], B.x, B.y);
                hmma(acc2[j] + 4, a1f[4], a1f[5], a1f[6], a1f[7], B.z, B.w);
                hmma(acc2[j] + 4, a2f[4], a2f[5], a2f[6], a2f[7], B.x, B.y);
            }

            if (ks == 19) {
                #pragma unroll
                for (int j = 0; j < 8; ++j) {
                    int col = (hh * 32 + wn2 * 8 + j) * 8 + 2 * q;
                    #pragma unroll
                    for (int e = 0; e < 4; ++e) {
                        size_t gr = (size_t)(rowbase + r0 + e * 8);
                        float2 p;
                        p.x = acc2[j][2 * e]     * scv[e];
                        p.y = acc2[j][2 * e + 1] * scv[e];
                        *(float2*)(out_part + gr * CDIM + col) = p;
                    }
                }
            }

            if (s + 2 < 40) {
                __syncthreads();   // everyone done reading stage s&1 before refill
                int s2 = s + 2;
                int hh2 = s2 / 20, ks2 = s2 % 20;
                #pragma unroll
                for (int it = 0; it < 4; ++it) {
                    int i = tid + it * 256;
                    int jj = i >> 5;
                    cp16(sb + OFF_G2 + (u32)((s & 1) * ST2 + i * 16),
                         &g_B2[(hh2 * 32 + jj) * 640 + ks2 * 32 + (i & 31)]);
                }
                CP_COMMIT();
            }
        }
    }
}

// ---------------------------------------------------------------------------
extern "C" void kernel_launch(void* const* d_in, const int* in_sizes, int n_in,
                              void* d_out, int out_size) {
    const float* X  = (const float*)d_in[0];
    const float* W  = (const float*)d_in[1];
    const float* wp = (const float*)d_in[2];
    const float* bp = (const float*)d_in[3];
    const float* wi = (const float*)d_in[4];
    const float* bi = (const float*)d_in[5];

    int N = in_sizes[0] / CDIM;   // 131072

    float* out      = (float*)d_out;
    float* out_sem  = out;                                   // [N, 512]
    float* out_att  = out + (size_t)N * CDIM;                // [N, 10]
    float* out_semm = out_att + (size_t)N * LCLS;            // [10, 512]
    float* out_part = out_semm + (size_t)LCLS * CDIM;        // [N, 512]

    sem_build_kernel<<<1, 512>>>(W, wp, bp, wi, bi, out_semm);
    bfrag1_kernel<<<(40 * 32 * 32 + 255) / 256, 256>>>(W);
    bfrag2_kernel<<<(64 * 20 * 32 + 255) / 256, 256>>>(W);

    cudaFuncSetAttribute(fused_kernel,
                         cudaFuncAttributeMaxDynamicSharedMemorySize, SMEM_BYTES);
    fused_kernel<<<N / BM, THREADS, SMEM_BYTES>>>(X, out_sem, out_att, out_part);
}